// round 1
// baseline (speedup 1.0000x reference)
#include <cuda_runtime.h>
#include <cstdint>

// Problem constants (shapes fixed by the reference)
#define NMAX 50000
#define EMAX 660000   // E (600000) + N self loops (50000), padded
#define HD   128

// ---------------- device scratch (no allocations allowed) ----------------
__device__ float g_h[NMAX * HD];     // GEMM output of current layer
__device__ float g_agg[NMAX * HD];   // aggregation output / next GEMM input
__device__ float g_ssrc[NMAX];
__device__ float g_sdst[NMAX];
__device__ int   g_cnt[NMAX];
__device__ int   g_wptr[NMAX];
__device__ int   g_rowptr[NMAX + 1];
__device__ int   g_col[EMAX];

// ---------------- CSR build ----------------
__global__ void zero_kernel(int n) {
    int i = blockIdx.x * blockDim.x + threadIdx.x;
    if (i < n) g_cnt[i] = 0;
}

__global__ void hist_kernel(const int* __restrict__ dst, int E) {
    int i = blockIdx.x * blockDim.x + threadIdx.x;
    if (i < E) atomicAdd(&g_cnt[dst[i]], 1);
}

// single-block scan over n (+1 per node for self loop)
__global__ void scan_kernel(int n) {
    __shared__ int sh[1024];
    __shared__ int carry;
    int t = threadIdx.x;
    if (t == 0) carry = 0;
    __syncthreads();
    for (int base = 0; base < n; base += 1024) {
        int i = base + t;
        int v = (i < n) ? (g_cnt[i] + 1) : 0;
        sh[t] = v;
        __syncthreads();
        #pragma unroll
        for (int o = 1; o < 1024; o <<= 1) {
            int tmp = (t >= o) ? sh[t - o] : 0;
            __syncthreads();
            sh[t] += tmp;
            __syncthreads();
        }
        int excl = carry + sh[t] - v;
        if (i < n) { g_rowptr[i] = excl; g_wptr[i] = excl; }
        __syncthreads();
        if (t == 0) carry += sh[1023];
        __syncthreads();
    }
    if (threadIdx.x == 0) g_rowptr[n] = carry;
}

__global__ void fill_kernel(const int* __restrict__ src, const int* __restrict__ dst,
                            int E, int n) {
    int i = blockIdx.x * blockDim.x + threadIdx.x;
    if (i < E) {
        int d = dst[i];
        int p = atomicAdd(&g_wptr[d], 1);
        g_col[p] = src[i];
    } else if (i < E + n) {
        int v = i - E;                      // self loop
        int p = atomicAdd(&g_wptr[v], 1);
        g_col[p] = v;
    }
}

// ---------------- GEMM: O[n,DOUT] = act(X + bias) @ W ----------------
__device__ __forceinline__ float silu(float v) { return v / (1.0f + __expf(-v)); }

template<int DOUT, bool ACT>
__global__ __launch_bounds__(256) void gemm_kernel(
    const float* __restrict__ X, const float* __restrict__ W,
    const float* __restrict__ bin, float* __restrict__ O, int n)
{
    constexpr int BM = 128, BK = 32;
    constexpr int TN = DOUT / 16;        // 8 (DOUT=128) or 4 (DOUT=64)
    __shared__ float xs[BM][BK + 1];
    __shared__ float ws[BK * DOUT];

    const int tid = threadIdx.x;
    const int tx = tid & 15;
    const int ty = tid >> 4;
    const int row0 = blockIdx.x * BM;
    const int q = tid & 7;               // k-quad for loads
    const int r = tid >> 3;              // row-in-group 0..31

    float acc[8][TN];
    #pragma unroll
    for (int i = 0; i < 8; i++)
        #pragma unroll
        for (int j = 0; j < TN; j++) acc[i][j] = 0.0f;

    for (int k0 = 0; k0 < HD; k0 += BK) {
        // load X tile (with fused bias + SiLU on input when ACT)
        #pragma unroll
        for (int rb = 0; rb < BM; rb += 32) {
            int row = row0 + rb + r;
            float4 v = make_float4(0.f, 0.f, 0.f, 0.f);
            if (row < n) v = *(const float4*)(X + (size_t)row * HD + k0 + q * 4);
            if (ACT) {
                v.x = silu(v.x + bin[k0 + q * 4 + 0]);
                v.y = silu(v.y + bin[k0 + q * 4 + 1]);
                v.z = silu(v.z + bin[k0 + q * 4 + 2]);
                v.w = silu(v.w + bin[k0 + q * 4 + 3]);
            }
            xs[rb + r][q * 4 + 0] = v.x;
            xs[rb + r][q * 4 + 1] = v.y;
            xs[rb + r][q * 4 + 2] = v.z;
            xs[rb + r][q * 4 + 3] = v.w;
        }
        // load W chunk (rows k0..k0+31 are contiguous)
        #pragma unroll
        for (int i = tid; i < BK * DOUT / 4; i += 256)
            ((float4*)ws)[i] = ((const float4*)(W + (size_t)k0 * DOUT))[i];
        __syncthreads();

        #pragma unroll
        for (int k = 0; k < BK; k++) {
            float a[8];
            #pragma unroll
            for (int i = 0; i < 8; i++) a[i] = xs[ty * 8 + i][k];
            float4 b0 = *(const float4*)&ws[k * DOUT + tx * 4];
            #pragma unroll
            for (int i = 0; i < 8; i++) {
                acc[i][0] += a[i] * b0.x;
                acc[i][1] += a[i] * b0.y;
                acc[i][2] += a[i] * b0.z;
                acc[i][3] += a[i] * b0.w;
            }
            if constexpr (TN == 8) {
                float4 b1 = *(const float4*)&ws[k * DOUT + DOUT / 2 + tx * 4];
                #pragma unroll
                for (int i = 0; i < 8; i++) {
                    acc[i][4] += a[i] * b1.x;
                    acc[i][5] += a[i] * b1.y;
                    acc[i][6] += a[i] * b1.z;
                    acc[i][7] += a[i] * b1.w;
                }
            }
        }
        __syncthreads();
    }

    #pragma unroll
    for (int i = 0; i < 8; i++) {
        int row = row0 + ty * 8 + i;
        if (row < n) {
            *(float4*)(O + (size_t)row * DOUT + tx * 4) =
                make_float4(acc[i][0], acc[i][1], acc[i][2], acc[i][3]);
            if constexpr (TN == 8) {
                *(float4*)(O + (size_t)row * DOUT + DOUT / 2 + tx * 4) =
                    make_float4(acc[i][4], acc[i][5], acc[i][6], acc[i][7]);
            }
        }
    }
}

// ---------------- attention scores: s_src = h.a_src, s_dst = h.a_dst ----------------
template<int DOUT>
__global__ __launch_bounds__(256) void s_kernel(const float* __restrict__ Hin,
    const float* __restrict__ av_s, const float* __restrict__ av_d, int n)
{
    int gw = (blockIdx.x * blockDim.x + threadIdx.x) >> 5;
    int lane = threadIdx.x & 31;
    if (gw >= n) return;
    float ds = 0.f, dd = 0.f;
    if constexpr (DOUT == 128) {
        float4 hv = *(const float4*)(Hin + (size_t)gw * 128 + lane * 4);
        float4 a = *(const float4*)(av_s + lane * 4);
        float4 b = *(const float4*)(av_d + lane * 4);
        ds = hv.x * a.x + hv.y * a.y + hv.z * a.z + hv.w * a.w;
        dd = hv.x * b.x + hv.y * b.y + hv.z * b.z + hv.w * b.w;
    } else {
        float2 hv = *(const float2*)(Hin + (size_t)gw * 64 + lane * 2);
        float2 a = *(const float2*)(av_s + lane * 2);
        float2 b = *(const float2*)(av_d + lane * 2);
        ds = hv.x * a.x + hv.y * a.y;
        dd = hv.x * b.x + hv.y * b.y;
    }
    #pragma unroll
    for (int o = 16; o; o >>= 1) {
        ds += __shfl_xor_sync(0xffffffffu, ds, o);
        dd += __shfl_xor_sync(0xffffffffu, dd, o);
    }
    if (lane == 0) { g_ssrc[gw] = ds; g_sdst[gw] = dd; }
}

// ---------------- aggregation: warp per destination node ----------------
template<int DOUT>
__global__ __launch_bounds__(256) void agg_kernel(const float* __restrict__ Hin,
                                                  float* __restrict__ out, int n)
{
    int gw = (blockIdx.x * blockDim.x + threadIdx.x) >> 5;
    int lane = threadIdx.x & 31;
    if (gw >= n) return;
    int beg = g_rowptr[gw], end = g_rowptr[gw + 1];
    float sd = g_sdst[gw];

    // pass 1: per-node max of leaky_relu(s_src[src] + s_dst[dst])
    float m = -1e30f;
    for (int j = beg + lane; j < end; j += 32) {
        float v = g_ssrc[g_col[j]] + sd;
        v = v > 0.f ? v : 0.2f * v;
        m = fmaxf(m, v);
    }
    #pragma unroll
    for (int o = 16; o; o >>= 1) m = fmaxf(m, __shfl_xor_sync(0xffffffffu, m, o));

    // pass 2: accumulate sum(exp * h[src]) and denom
    constexpr int V = DOUT / 32;
    float acc[V];
    #pragma unroll
    for (int t = 0; t < V; t++) acc[t] = 0.f;
    float denom = 0.f;
    for (int j = beg; j < end; j++) {
        int s = g_col[j];
        float v = g_ssrc[s] + sd;
        v = v > 0.f ? v : 0.2f * v;
        float ex = __expf(v - m);
        denom += ex;
        if constexpr (V == 4) {
            float4 hv = *(const float4*)(Hin + (size_t)s * DOUT + lane * 4);
            acc[0] += ex * hv.x; acc[1] += ex * hv.y;
            acc[2] += ex * hv.z; acc[3] += ex * hv.w;
        } else {
            float2 hv = *(const float2*)(Hin + (size_t)s * DOUT + lane * 2);
            acc[0] += ex * hv.x; acc[1] += ex * hv.y;
        }
    }
    float inv = 1.0f / denom;
    if constexpr (V == 4) {
        *(float4*)(out + (size_t)gw * DOUT + lane * 4) =
            make_float4(acc[0] * inv, acc[1] * inv, acc[2] * inv, acc[3] * inv);
    } else {
        *(float2*)(out + (size_t)gw * DOUT + lane * 2) =
            make_float2(acc[0] * inv, acc[1] * inv);
    }
}

// ---------------- final: bias + log_softmax over 64 classes ----------------
__global__ __launch_bounds__(256) void lsm_kernel(const float* __restrict__ A,
    const float* __restrict__ b, float* __restrict__ out, int n)
{
    int gw = (blockIdx.x * blockDim.x + threadIdx.x) >> 5;
    int lane = threadIdx.x & 31;
    if (gw >= n) return;
    float2 v = *(const float2*)(A + (size_t)gw * 64 + lane * 2);
    float2 bb = *(const float2*)(b + lane * 2);
    v.x += bb.x; v.y += bb.y;
    float m = fmaxf(v.x, v.y);
    #pragma unroll
    for (int o = 16; o; o >>= 1) m = fmaxf(m, __shfl_xor_sync(0xffffffffu, m, o));
    float s = __expf(v.x - m) + __expf(v.y - m);
    #pragma unroll
    for (int o = 16; o; o >>= 1) s += __shfl_xor_sync(0xffffffffu, s, o);
    float lse = m + __logf(s);
    *(float2*)(out + (size_t)gw * 64 + lane * 2) = make_float2(v.x - lse, v.y - lse);
}

// ---------------- launch ----------------
extern "C" void kernel_launch(void* const* d_in, const int* in_sizes, int n_in,
                              void* d_out, int out_size)
{
    const float* x   = (const float*)d_in[0];
    const int*   ei  = (const int*)d_in[1];
    const float* W0  = (const float*)d_in[2];
    const float* as0 = (const float*)d_in[3];
    const float* ad0 = (const float*)d_in[4];
    const float* b0  = (const float*)d_in[5];
    const float* W1  = (const float*)d_in[6];
    const float* as1 = (const float*)d_in[7];
    const float* ad1 = (const float*)d_in[8];
    const float* b1  = (const float*)d_in[9];
    const float* W2  = (const float*)d_in[10];
    const float* as2 = (const float*)d_in[11];
    const float* ad2 = (const float*)d_in[12];
    const float* b2  = (const float*)d_in[13];

    int n = in_sizes[0] / HD;     // 50000
    int E = in_sizes[1] / 2;      // 600000
    const int* src = ei;
    const int* dst = ei + E;

    float *h = nullptr, *agg = nullptr;
    cudaGetSymbolAddress((void**)&h, g_h);
    cudaGetSymbolAddress((void**)&agg, g_agg);

    // CSR build (by destination, with self loops appended)
    zero_kernel<<<(n + 255) / 256, 256>>>(n);
    hist_kernel<<<(E + 255) / 256, 256>>>(dst, E);
    scan_kernel<<<1, 1024>>>(n);
    fill_kernel<<<(E + n + 255) / 256, 256>>>(src, dst, E, n);

    int gemmg = (n + 127) / 128;
    int warpg = (n * 32 + 255) / 256;

    // layer 0
    gemm_kernel<128, false><<<gemmg, 256>>>(x, W0, nullptr, h, n);
    s_kernel<128><<<warpg, 256>>>(h, as0, ad0, n);
    agg_kernel<128><<<warpg, 256>>>(h, agg, n);
    // layer 1 (bias0 + SiLU fused into GEMM input)
    gemm_kernel<128, true><<<gemmg, 256>>>(agg, W1, b0, h, n);
    s_kernel<128><<<warpg, 256>>>(h, as1, ad1, n);
    agg_kernel<128><<<warpg, 256>>>(h, agg, n);
    // layer 2
    gemm_kernel<64, true><<<gemmg, 256>>>(agg, W2, b1, h, n);
    s_kernel<64><<<warpg, 256>>>(h, as2, ad2, n);
    agg_kernel<64><<<warpg, 256>>>(h, agg, n);
    // bias2 + log_softmax
    lsm_kernel<<<warpg, 256>>>(agg, b2, (float*)d_out, n);
}

// round 2
// speedup vs baseline: 1.1885x; 1.1885x over previous
#include <cuda_runtime.h>
#include <cstdint>

#define NMAX 50000
#define EMAX 660000
#define HD   128

// ---------------- device scratch ----------------
__device__ float g_h[NMAX * HD];
__device__ float g_agg[NMAX * HD];
__device__ float g_ssrc[NMAX];
__device__ float g_sdst[NMAX];
__device__ int   g_cnt[NMAX];
__device__ int   g_wptr[NMAX];
__device__ int   g_rowptr[NMAX + 1];
__device__ int   g_col[EMAX];

// packed fp32x2 FMA (Blackwell FFMA2 — ptxas never emits this from C++)
#define FMA_F32X2(d, a, b, c) \
    asm("fma.rn.f32x2 %0, %1, %2, %3;" : "=l"(d) : "l"(a), "l"(b), "l"(c))
#define PACK_DUP_F32X2(out, v) \
    asm("mov.b64 %0, {%1, %1};" : "=l"(out) : "r"(__float_as_uint(v)))

union U2 { unsigned long long u; float2 f; };

// ---------------- CSR build ----------------
__global__ void zero_kernel(int n) {
    int i = blockIdx.x * blockDim.x + threadIdx.x;
    if (i < n) g_cnt[i] = 0;
}

__global__ void hist_kernel(const int* __restrict__ dst, int E) {
    int i = blockIdx.x * blockDim.x + threadIdx.x;
    if (i < E) atomicAdd(&g_cnt[dst[i]], 1);
}

// one-pass single-block scan: items-per-thread serial + warp-shuffle block scan
__global__ __launch_bounds__(1024) void scan_kernel(int n) {
    const int t = threadIdx.x;
    const int items = (n + 1023) / 1024;
    const int base = t * items;
    int sum = 0;
    for (int i = 0; i < items; i++) {
        int idx = base + i;
        if (idx < n) sum += g_cnt[idx] + 1;
    }
    __shared__ int wsum[32];
    int lane = t & 31, warp = t >> 5;
    int v = sum;
    #pragma unroll
    for (int o = 1; o < 32; o <<= 1) {
        int u = __shfl_up_sync(0xffffffffu, v, o);
        if (lane >= o) v += u;
    }
    if (lane == 31) wsum[warp] = v;
    __syncthreads();
    if (warp == 0) {
        int w = wsum[lane];
        #pragma unroll
        for (int o = 1; o < 32; o <<= 1) {
            int u = __shfl_up_sync(0xffffffffu, w, o);
            if (lane >= o) w += u;
        }
        wsum[lane] = w;
    }
    __syncthreads();
    int run = v - sum + (warp ? wsum[warp - 1] : 0);   // exclusive prefix
    for (int i = 0; i < items; i++) {
        int idx = base + i;
        if (idx < n) {
            g_rowptr[idx] = run;
            g_wptr[idx] = run;
            run += g_cnt[idx] + 1;
        }
    }
    if (t == 1023) g_rowptr[n] = run;
}

__global__ void fill_kernel(const int* __restrict__ src, const int* __restrict__ dst,
                            int E, int n) {
    int i = blockIdx.x * blockDim.x + threadIdx.x;
    if (i < E) {
        int p = atomicAdd(&g_wptr[dst[i]], 1);
        g_col[p] = src[i];
    } else if (i < E + n) {
        int vtx = i - E;
        int p = atomicAdd(&g_wptr[vtx], 1);
        g_col[p] = vtx;
    }
}

// ---------------- GEMM with FFMA2 + fused attention-score epilogue ----------------
__device__ __forceinline__ float silu(float v) { return v / (1.0f + __expf(-v)); }

// O[n,DOUT] = act(X + bias_in) @ W ; also g_ssrc = O @ a_src, g_sdst = O @ a_dst
template<int DOUT, bool ACT>
__global__ __launch_bounds__(256) void gemm_kernel(
    const float* __restrict__ X, const float* __restrict__ W,
    const float* __restrict__ bin,
    const float* __restrict__ av_s, const float* __restrict__ av_d,
    float* __restrict__ O, int n)
{
    constexpr int BM = 128, BK = 32;
    constexpr int TN = DOUT / 16;        // scalar cols per thread: 8 or 4
    constexpr int XST = 130;             // padded row stride (banks + 8B align)
    __shared__ float xs[BK * XST];       // transposed: xs[k*XST + row]
    __shared__ float ws[BK * DOUT];

    const int tid = threadIdx.x;
    const int tx = tid & 15;
    const int ty = tid >> 4;
    const int row0 = blockIdx.x * BM;
    const int q = tid & 7;
    const int r = tid >> 3;

    // preload attention vectors for this thread's columns
    float as_c[TN], ad_c[TN];
    #pragma unroll
    for (int j = 0; j < TN; j++) {
        int col = (j < 4) ? tx * 4 + j : 64 + tx * 4 + (j - 4);
        as_c[j] = av_s[col];
        ad_c[j] = av_d[col];
    }

    unsigned long long acc2[4][TN];      // row-pairs x cols
    #pragma unroll
    for (int i = 0; i < 4; i++)
        #pragma unroll
        for (int j = 0; j < TN; j++) acc2[i][j] = 0ull;

    for (int k0 = 0; k0 < HD; k0 += BK) {
        // load X tile, store k-major transposed
        #pragma unroll
        for (int rb = 0; rb < 4; rb++) {
            int rl = rb * 32 + r;
            int row = row0 + rl;
            float4 v = make_float4(0.f, 0.f, 0.f, 0.f);
            if (row < n) v = *(const float4*)(X + (size_t)row * HD + k0 + q * 4);
            if (ACT) {
                v.x = silu(v.x + bin[k0 + q * 4 + 0]);
                v.y = silu(v.y + bin[k0 + q * 4 + 1]);
                v.z = silu(v.z + bin[k0 + q * 4 + 2]);
                v.w = silu(v.w + bin[k0 + q * 4 + 3]);
            }
            xs[(q * 4 + 0) * XST + rl] = v.x;
            xs[(q * 4 + 1) * XST + rl] = v.y;
            xs[(q * 4 + 2) * XST + rl] = v.z;
            xs[(q * 4 + 3) * XST + rl] = v.w;
        }
        #pragma unroll
        for (int i = tid; i < BK * DOUT / 4; i += 256)
            ((float4*)ws)[i] = ((const float4*)(W + (size_t)k0 * DOUT))[i];
        __syncthreads();

        #pragma unroll
        for (int k = 0; k < BK; k++) {
            unsigned long long a2[4];
            const unsigned long long* xp =
                (const unsigned long long*)&xs[k * XST + ty * 8];
            #pragma unroll
            for (int i = 0; i < 4; i++) a2[i] = xp[i];

            unsigned long long b2[TN];
            float4 b0 = *(const float4*)&ws[k * DOUT + tx * 4];
            PACK_DUP_F32X2(b2[0], b0.x);
            PACK_DUP_F32X2(b2[1], b0.y);
            PACK_DUP_F32X2(b2[2], b0.z);
            PACK_DUP_F32X2(b2[3], b0.w);
            if constexpr (TN == 8) {
                float4 b1 = *(const float4*)&ws[k * DOUT + 64 + tx * 4];
                PACK_DUP_F32X2(b2[4], b1.x);
                PACK_DUP_F32X2(b2[5], b1.y);
                PACK_DUP_F32X2(b2[6], b1.z);
                PACK_DUP_F32X2(b2[7], b1.w);
            }
            #pragma unroll
            for (int i = 0; i < 4; i++)
                #pragma unroll
                for (int j = 0; j < TN; j++)
                    FMA_F32X2(acc2[i][j], a2[i], b2[j], acc2[i][j]);
        }
        __syncthreads();
    }

    // epilogue: store O rows + fused s_src/s_dst with 16-lane shuffle reduce
    #pragma unroll
    for (int i2 = 0; i2 < 4; i2++) {
        #pragma unroll
        for (int h = 0; h < 2; h++) {
            int row = row0 + ty * 8 + i2 * 2 + h;
            float vals[TN];
            #pragma unroll
            for (int j = 0; j < TN; j++) {
                U2 u; u.u = acc2[i2][j];
                vals[j] = h ? u.f.y : u.f.x;
            }
            float ss = 0.f, sd = 0.f;
            #pragma unroll
            for (int j = 0; j < TN; j++) {
                ss += vals[j] * as_c[j];
                sd += vals[j] * ad_c[j];
            }
            #pragma unroll
            for (int o = 8; o; o >>= 1) {
                ss += __shfl_xor_sync(0xffffffffu, ss, o);
                sd += __shfl_xor_sync(0xffffffffu, sd, o);
            }
            if (row < n) {
                *(float4*)(O + (size_t)row * DOUT + tx * 4) =
                    make_float4(vals[0], vals[1], vals[2], vals[3]);
                if constexpr (TN == 8) {
                    *(float4*)(O + (size_t)row * DOUT + 64 + tx * 4) =
                        make_float4(vals[4], vals[5], vals[6], vals[7]);
                }
                if (tx == 0) { g_ssrc[row] = ss; g_sdst[row] = sd; }
            }
        }
    }
}

// ---------------- aggregation (warp per destination node) ----------------
template<int DOUT, bool FINAL>
__global__ __launch_bounds__(256) void agg_kernel(const float* __restrict__ Hin,
    float* __restrict__ out, const float* __restrict__ bias, int n)
{
    int gw = (blockIdx.x * blockDim.x + threadIdx.x) >> 5;
    int lane = threadIdx.x & 31;
    if (gw >= n) return;
    int beg = g_rowptr[gw], end = g_rowptr[gw + 1];
    float sd = g_sdst[gw];

    // pass 1: max over neighborhood
    float m = -1e30f;
    for (int j = beg + lane; j < end; j += 32) {
        float v = g_ssrc[g_col[j]] + sd;
        v = v > 0.f ? v : 0.2f * v;
        m = fmaxf(m, v);
    }
    #pragma unroll
    for (int o = 16; o; o >>= 1) m = fmaxf(m, __shfl_xor_sync(0xffffffffu, m, o));

    // pass 2: sum(exp * h[src]) and denom, unrolled x2 for MLP
    constexpr int V = DOUT / 32;
    float acc[V];
    #pragma unroll
    for (int t = 0; t < V; t++) acc[t] = 0.f;
    float denom = 0.f;
    int j = beg;
    for (; j + 1 < end; j += 2) {
        int s0 = g_col[j], s1 = g_col[j + 1];
        float v0 = g_ssrc[s0] + sd, v1 = g_ssrc[s1] + sd;
        v0 = v0 > 0.f ? v0 : 0.2f * v0;
        v1 = v1 > 0.f ? v1 : 0.2f * v1;
        float e0 = __expf(v0 - m), e1 = __expf(v1 - m);
        denom += e0 + e1;
        if constexpr (V == 4) {
            float4 h0 = *(const float4*)(Hin + (size_t)s0 * DOUT + lane * 4);
            float4 h1 = *(const float4*)(Hin + (size_t)s1 * DOUT + lane * 4);
            acc[0] += e0 * h0.x + e1 * h1.x;
            acc[1] += e0 * h0.y + e1 * h1.y;
            acc[2] += e0 * h0.z + e1 * h1.z;
            acc[3] += e0 * h0.w + e1 * h1.w;
        } else {
            float2 h0 = *(const float2*)(Hin + (size_t)s0 * DOUT + lane * 2);
            float2 h1 = *(const float2*)(Hin + (size_t)s1 * DOUT + lane * 2);
            acc[0] += e0 * h0.x + e1 * h1.x;
            acc[1] += e0 * h0.y + e1 * h1.y;
        }
    }
    if (j < end) {
        int s0 = g_col[j];
        float v0 = g_ssrc[s0] + sd;
        v0 = v0 > 0.f ? v0 : 0.2f * v0;
        float e0 = __expf(v0 - m);
        denom += e0;
        if constexpr (V == 4) {
            float4 h0 = *(const float4*)(Hin + (size_t)s0 * DOUT + lane * 4);
            acc[0] += e0 * h0.x; acc[1] += e0 * h0.y;
            acc[2] += e0 * h0.z; acc[3] += e0 * h0.w;
        } else {
            float2 h0 = *(const float2*)(Hin + (size_t)s0 * DOUT + lane * 2);
            acc[0] += e0 * h0.x; acc[1] += e0 * h0.y;
        }
    }
    float inv = 1.0f / denom;

    if constexpr (!FINAL) {
        if constexpr (V == 4) {
            *(float4*)(out + (size_t)gw * DOUT + lane * 4) =
                make_float4(acc[0] * inv, acc[1] * inv, acc[2] * inv, acc[3] * inv);
        } else {
            *(float2*)(out + (size_t)gw * DOUT + lane * 2) =
                make_float2(acc[0] * inv, acc[1] * inv);
        }
    } else {
        // fused bias + log_softmax over 64 classes (V==2)
        float2 bb = *(const float2*)(bias + lane * 2);
        float x0 = acc[0] * inv + bb.x;
        float x1 = acc[1] * inv + bb.y;
        float mm = fmaxf(x0, x1);
        #pragma unroll
        for (int o = 16; o; o >>= 1) mm = fmaxf(mm, __shfl_xor_sync(0xffffffffu, mm, o));
        float s = __expf(x0 - mm) + __expf(x1 - mm);
        #pragma unroll
        for (int o = 16; o; o >>= 1) s += __shfl_xor_sync(0xffffffffu, s, o);
        float lse = mm + __logf(s);
        *(float2*)(out + (size_t)gw * 64 + lane * 2) = make_float2(x0 - lse, x1 - lse);
    }
}

// ---------------- launch ----------------
extern "C" void kernel_launch(void* const* d_in, const int* in_sizes, int n_in,
                              void* d_out, int out_size)
{
    const float* x   = (const float*)d_in[0];
    const int*   ei  = (const int*)d_in[1];
    const float* W0  = (const float*)d_in[2];
    const float* as0 = (const float*)d_in[3];
    const float* ad0 = (const float*)d_in[4];
    const float* b0  = (const float*)d_in[5];
    const float* W1  = (const float*)d_in[6];
    const float* as1 = (const float*)d_in[7];
    const float* ad1 = (const float*)d_in[8];
    const float* b1  = (const float*)d_in[9];
    const float* W2  = (const float*)d_in[10];
    const float* as2 = (const float*)d_in[11];
    const float* ad2 = (const float*)d_in[12];
    const float* b2  = (const float*)d_in[13];

    int n = in_sizes[0] / HD;
    int E = in_sizes[1] / 2;
    const int* src = ei;
    const int* dst = ei + E;

    float *h = nullptr, *agg = nullptr;
    cudaGetSymbolAddress((void**)&h, g_h);
    cudaGetSymbolAddress((void**)&agg, g_agg);

    zero_kernel<<<(n + 255) / 256, 256>>>(n);
    hist_kernel<<<(E + 255) / 256, 256>>>(dst, E);
    scan_kernel<<<1, 1024>>>(n);
    fill_kernel<<<(E + n + 255) / 256, 256>>>(src, dst, E, n);

    int gemmg = (n + 127) / 128;
    int warpg = (n * 32 + 255) / 256;

    gemm_kernel<128, false><<<gemmg, 256>>>(x, W0, nullptr, as0, ad0, h, n);
    agg_kernel<128, false><<<warpg, 256>>>(h, agg, nullptr, n);

    gemm_kernel<128, true><<<gemmg, 256>>>(agg, W1, b0, as1, ad1, h, n);
    agg_kernel<128, false><<<warpg, 256>>>(h, agg, nullptr, n);

    gemm_kernel<64, true><<<gemmg, 256>>>(agg, W2, b1, as2, ad2, h, n);
    agg_kernel<64, true><<<warpg, 256>>>(h, (float*)d_out, b2, n);
}

// round 5
// speedup vs baseline: 1.2285x; 1.0336x over previous
#include <cuda_runtime.h>
#include <cuda_bf16.h>
#include <cstdint>

#define NMAX 50000
#define EMAX 660000
#define HD   128

// ---------------- device scratch ----------------
__device__ __align__(16) float g_h[NMAX * HD];
__device__ __align__(16) float g_agg[NMAX * HD];
__device__ __align__(16) float g_ssrc[NMAX];
__device__ __align__(16) float g_sdst[NMAX];
__device__ __align__(16) int   g_cnt[NMAX];
__device__ __align__(16) int   g_wptr[NMAX];
__device__ __align__(16) int   g_rowptr[NMAX + 1];
__device__ __align__(16) int   g_col[EMAX];
// B fragments in mma order: [nb][ks][lane] -> {bhi0, bhi1, blo0, blo1}
__device__ uint4 g_bf0[16 * 8 * 32];
__device__ uint4 g_bf1[16 * 8 * 32];
__device__ uint4 g_bf2[8 * 8 * 32];

__device__ __forceinline__ uint32_t smem_u32(const void* p) {
    uint32_t a;
    asm("{ .reg .u64 t; cvta.to.shared.u64 t, %1; cvt.u32.u64 %0, t; }" : "=r"(a) : "l"(p));
    return a;
}
__device__ __forceinline__ void ldmatrix_x4(uint32_t* r, uint32_t addr) {
    asm volatile("ldmatrix.sync.aligned.m8n8.x4.shared.b16 {%0,%1,%2,%3}, [%4];"
                 : "=r"(r[0]), "=r"(r[1]), "=r"(r[2]), "=r"(r[3]) : "r"(addr));
}
__device__ __forceinline__ void mma16816(float* c, const uint32_t* a, uint32_t b0, uint32_t b1) {
    asm volatile(
        "mma.sync.aligned.m16n8k16.row.col.f32.bf16.bf16.f32 "
        "{%0,%1,%2,%3}, {%4,%5,%6,%7}, {%8,%9}, {%0,%1,%2,%3};"
        : "+f"(c[0]), "+f"(c[1]), "+f"(c[2]), "+f"(c[3])
        : "r"(a[0]), "r"(a[1]), "r"(a[2]), "r"(a[3]), "r"(b0), "r"(b1));
}
__device__ __forceinline__ uint32_t pack_hi(float a, float b) {
    __nv_bfloat162 h = __floats2bfloat162_rn(a, b);
    return *(uint32_t*)&h;
}

// ---------------- CSR build ----------------
__global__ void zero_kernel(int n) {
    int i = blockIdx.x * blockDim.x + threadIdx.x;
    if (i < n) g_cnt[i] = 0;
}
__global__ void hist_kernel(const int* __restrict__ dst, int E) {
    int b = (blockIdx.x * blockDim.x + threadIdx.x) * 4;
    #pragma unroll
    for (int j = 0; j < 4; j++)
        if (b + j < E) atomicAdd(&g_cnt[dst[b + j]], 1);
}
__global__ __launch_bounds__(1024) void scan_kernel(int n) {
    const int t = threadIdx.x;
    const int items = (n + 1023) / 1024;
    const int base = t * items;
    int sum = 0;
    for (int i = 0; i < items; i++) {
        int idx = base + i;
        if (idx < n) sum += g_cnt[idx] + 1;
    }
    __shared__ int wsum[32];
    int lane = t & 31, warp = t >> 5;
    int v = sum;
    #pragma unroll
    for (int o = 1; o < 32; o <<= 1) {
        int u = __shfl_up_sync(0xffffffffu, v, o);
        if (lane >= o) v += u;
    }
    if (lane == 31) wsum[warp] = v;
    __syncthreads();
    if (warp == 0) {
        int w = wsum[lane];
        #pragma unroll
        for (int o = 1; o < 32; o <<= 1) {
            int u = __shfl_up_sync(0xffffffffu, w, o);
            if (lane >= o) w += u;
        }
        wsum[lane] = w;
    }
    __syncthreads();
    int run = v - sum + (warp ? wsum[warp - 1] : 0);
    for (int i = 0; i < items; i++) {
        int idx = base + i;
        if (idx < n) {
            g_rowptr[idx] = run;
            g_wptr[idx] = run;
            run += g_cnt[idx] + 1;
        }
    }
    if (t == 1023) g_rowptr[n] = run;
}
__global__ void fill_kernel(const int* __restrict__ src, const int* __restrict__ dst,
                            int E, int n) {
    int b = (blockIdx.x * blockDim.x + threadIdx.x) * 4;
    #pragma unroll
    for (int j = 0; j < 4; j++) {
        int i = b + j;
        if (i < E) {
            int p = atomicAdd(&g_wptr[dst[i]], 1);
            g_col[p] = src[i];
        } else if (i < E + n) {
            int vtx = i - E;
            int p = atomicAdd(&g_wptr[vtx], 1);
            g_col[p] = vtx;
        }
    }
}

// ---------------- W prep: pack B fragments (hi/lo bf16 split) ----------------
__global__ void wprep_kernel(const float* __restrict__ W0, const float* __restrict__ W1,
                             const float* __restrict__ W2) {
    int idx = blockIdx.x * blockDim.x + threadIdx.x;
    const float* W;
    uint4* out;
    int N, local;
    if (idx < 4096)       { W = W0; out = g_bf0; N = 128; local = idx; }
    else if (idx < 8192)  { W = W1; out = g_bf1; N = 128; local = idx - 4096; }
    else if (idx < 10240) { W = W2; out = g_bf2; N = 64;  local = idx - 8192; }
    else return;
    int lane = local & 31;
    int ks = (local >> 5) & 7;
    int nb = local >> 8;
    int g = lane >> 2, t = lane & 3;
    int nn = nb * 8 + g;
    int k0 = ks * 16 + t * 2;
    float w00 = W[(k0 + 0) * N + nn], w01 = W[(k0 + 1) * N + nn];
    float w10 = W[(k0 + 8) * N + nn], w11 = W[(k0 + 9) * N + nn];
    __nv_bfloat16 h00 = __float2bfloat16(w00), h01 = __float2bfloat16(w01);
    __nv_bfloat16 h10 = __float2bfloat16(w10), h11 = __float2bfloat16(w11);
    uint4 o;
    o.x = pack_hi(w00, w01);    // == packed(h00,h01) since rn conversion
    o.y = pack_hi(w10, w11);
    o.z = pack_hi(w00 - __bfloat162float(h00), w01 - __bfloat162float(h01));
    o.w = pack_hi(w10 - __bfloat162float(h10), w11 - __bfloat162float(h11));
    out[local] = o;
}

// ---------------- bf16 mma GEMM + fused attention-score epilogue ----------------
__device__ __forceinline__ float silu(float v) { return v / (1.0f + __expf(-v)); }

template<int DOUT, bool ACT>
__global__ __launch_bounds__(256) void gemm_mma(
    const float* __restrict__ X, const uint4* __restrict__ Bf,
    const float* __restrict__ bin,
    const float* __restrict__ av_s, const float* __restrict__ av_d,
    float* __restrict__ O, int n)
{
    constexpr int NSTEP = DOUT / 8;
    constexpr int AST = 136;                 // A smem row stride (bf16 elems)
    extern __shared__ __align__(16) char smem[];
    __nv_bfloat16* Ahi = (__nv_bfloat16*)smem;
    __nv_bfloat16* Alo = Ahi + 128 * AST;

    const int tid = threadIdx.x;
    const int wid = tid >> 5;
    const int lane = tid & 31;
    const int row0 = blockIdx.x * 128;

    // ---- stage A tile: f32 -> (bias+silu) -> bf16 hi/lo ----
    for (int i = tid; i < 4096; i += 256) {
        int row = i >> 5, c4 = (i & 31) * 4;
        float4 v = make_float4(0.f, 0.f, 0.f, 0.f);
        if (row0 + row < n) v = *(const float4*)(X + (size_t)(row0 + row) * HD + c4);
        if (ACT) {
            v.x = silu(v.x + bin[c4 + 0]);
            v.y = silu(v.y + bin[c4 + 1]);
            v.z = silu(v.z + bin[c4 + 2]);
            v.w = silu(v.w + bin[c4 + 3]);
        }
        __nv_bfloat162 h01 = __floats2bfloat162_rn(v.x, v.y);
        __nv_bfloat162 h23 = __floats2bfloat162_rn(v.z, v.w);
        __nv_bfloat162 l01 = __floats2bfloat162_rn(v.x - __low2float(h01), v.y - __high2float(h01));
        __nv_bfloat162 l23 = __floats2bfloat162_rn(v.z - __low2float(h23), v.w - __high2float(h23));
        *(__nv_bfloat162*)(Ahi + row * AST + c4)     = h01;
        *(__nv_bfloat162*)(Ahi + row * AST + c4 + 2) = h23;
        *(__nv_bfloat162*)(Alo + row * AST + c4)     = l01;
        *(__nv_bfloat162*)(Alo + row * AST + c4 + 2) = l23;
    }
    __syncthreads();

    float acc[NSTEP][4];
    #pragma unroll
    for (int i = 0; i < NSTEP; i++) {
        acc[i][0] = acc[i][1] = acc[i][2] = acc[i][3] = 0.f;
    }

    // ldmatrix source row/col for this lane
    const int arow = 16 * wid + (lane & 15);
    const int acol = (lane >> 4) * 8;
    const uint32_t ahi_base = smem_u32(Ahi + arow * AST + acol);
    const uint32_t alo_base = smem_u32(Alo + arow * AST + acol);

    #pragma unroll
    for (int ks = 0; ks < 8; ks++) {
        uint32_t ahi[4], alo[4];
        ldmatrix_x4(ahi, ahi_base + ks * 32);
        ldmatrix_x4(alo, alo_base + ks * 32);
        #pragma unroll
        for (int nb = 0; nb < NSTEP; nb++) {
            uint4 b = __ldg(&Bf[(nb * 8 + ks) * 32 + lane]);
            mma16816(acc[nb], ahi, b.x, b.y);   // hi*hi
            mma16816(acc[nb], ahi, b.z, b.w);   // hi*lo
            mma16816(acc[nb], alo, b.x, b.y);   // lo*hi
        }
    }

    // ---- epilogue: direct stores + fused s_src/s_dst ----
    const int g = lane >> 2, t = lane & 3;
    const int r0 = row0 + 16 * wid + g;
    const int r1 = r0 + 8;
    float ss0 = 0.f, sd0 = 0.f, ss1 = 0.f, sd1 = 0.f;
    #pragma unroll
    for (int nb = 0; nb < NSTEP; nb++) {
        int c = nb * 8 + t * 2;
        float a0 = __ldg(&av_s[c]), a1 = __ldg(&av_s[c + 1]);
        float d0 = __ldg(&av_d[c]), d1 = __ldg(&av_d[c + 1]);
        ss0 += acc[nb][0] * a0 + acc[nb][1] * a1;
        sd0 += acc[nb][0] * d0 + acc[nb][1] * d1;
        ss1 += acc[nb][2] * a0 + acc[nb][3] * a1;
        sd1 += acc[nb][2] * d0 + acc[nb][3] * d1;
        if (r0 < n) *(float2*)(O + (size_t)r0 * DOUT + c) = make_float2(acc[nb][0], acc[nb][1]);
        if (r1 < n) *(float2*)(O + (size_t)r1 * DOUT + c) = make_float2(acc[nb][2], acc[nb][3]);
    }
    #pragma unroll
    for (int o = 1; o <= 2; o <<= 1) {
        ss0 += __shfl_xor_sync(0xffffffffu, ss0, o);
        sd0 += __shfl_xor_sync(0xffffffffu, sd0, o);
        ss1 += __shfl_xor_sync(0xffffffffu, ss1, o);
        sd1 += __shfl_xor_sync(0xffffffffu, sd1, o);
    }
    if (t == 0) {
        if (r0 < n) { g_ssrc[r0] = ss0; g_sdst[r0] = sd0; }
        if (r1 < n) { g_ssrc[r1] = ss1; g_sdst[r1] = sd1; }
    }
}

// ---------------- aggregation (warp per destination node) ----------------
template<int DOUT, bool FINAL>
__global__ __launch_bounds__(256) void agg_kernel(const float* __restrict__ Hin,
    float* __restrict__ out, const float* __restrict__ bias, int n)
{
    int gw = (blockIdx.x * blockDim.x + threadIdx.x) >> 5;
    int lane = threadIdx.x & 31;
    if (gw >= n) return;
    int beg = g_rowptr[gw], end = g_rowptr[gw + 1];
    float sd = g_sdst[gw];

    float m = -1e30f;
    for (int j = beg + lane; j < end; j += 32) {
        float v = g_ssrc[g_col[j]] + sd;
        v = v > 0.f ? v : 0.2f * v;
        m = fmaxf(m, v);
    }
    #pragma unroll
    for (int o = 16; o; o >>= 1) m = fmaxf(m, __shfl_xor_sync(0xffffffffu, m, o));

    constexpr int V = DOUT / 32;
    float acc[V];
    #pragma unroll
    for (int t = 0; t < V; t++) acc[t] = 0.f;
    float denom = 0.f;
    int j = beg;
    for (; j + 1 < end; j += 2) {
        int s0 = g_col[j], s1 = g_col[j + 1];
        float v0 = g_ssrc[s0] + sd, v1 = g_ssrc[s1] + sd;
        v0 = v0 > 0.f ? v0 : 0.2f * v0;
        v1 = v1 > 0.f ? v1 : 0.2f * v1;
        float e0 = __expf(v0 - m), e1 = __expf(v1 - m);
        denom += e0 + e1;
        if constexpr (V == 4) {
            float4 h0 = *(const float4*)(Hin + (size_t)s0 * DOUT + lane * 4);
            float4 h1 = *(const float4*)(Hin + (size_t)s1 * DOUT + lane * 4);
            acc[0] += e0 * h0.x + e1 * h1.x;
            acc[1] += e0 * h0.y + e1 * h1.y;
            acc[2] += e0 * h0.z + e1 * h1.z;
            acc[3] += e0 * h0.w + e1 * h1.w;
        } else {
            float2 h0 = *(const float2*)(Hin + (size_t)s0 * DOUT + lane * 2);
            float2 h1 = *(const float2*)(Hin + (size_t)s1 * DOUT + lane * 2);
            acc[0] += e0 * h0.x + e1 * h1.x;
            acc[1] += e0 * h0.y + e1 * h1.y;
        }
    }
    if (j < end) {
        int s0 = g_col[j];
        float v0 = g_ssrc[s0] + sd;
        v0 = v0 > 0.f ? v0 : 0.2f * v0;
        float e0 = __expf(v0 - m);
        denom += e0;
        if constexpr (V == 4) {
            float4 h0 = *(const float4*)(Hin + (size_t)s0 * DOUT + lane * 4);
            acc[0] += e0 * h0.x; acc[1] += e0 * h0.y;
            acc[2] += e0 * h0.z; acc[3] += e0 * h0.w;
        } else {
            float2 h0 = *(const float2*)(Hin + (size_t)s0 * DOUT + lane * 2);
            acc[0] += e0 * h0.x; acc[1] += e0 * h0.y;
        }
    }
    float inv = 1.0f / denom;

    if constexpr (!FINAL) {
        if constexpr (V == 4) {
            *(float4*)(out + (size_t)gw * DOUT + lane * 4) =
                make_float4(acc[0] * inv, acc[1] * inv, acc[2] * inv, acc[3] * inv);
        } else {
            *(float2*)(out + (size_t)gw * DOUT + lane * 2) =
                make_float2(acc[0] * inv, acc[1] * inv);
        }
    } else {
        float2 bb = *(const float2*)(bias + lane * 2);
        float x0 = acc[0] * inv + bb.x;
        float x1 = acc[1] * inv + bb.y;
        float mm = fmaxf(x0, x1);
        #pragma unroll
        for (int o = 16; o; o >>= 1) mm = fmaxf(mm, __shfl_xor_sync(0xffffffffu, mm, o));
        float s = __expf(x0 - mm) + __expf(x1 - mm);
        #pragma unroll
        for (int o = 16; o; o >>= 1) s += __shfl_xor_sync(0xffffffffu, s, o);
        float lse = mm + __logf(s);
        *(float2*)(out + (size_t)gw * 64 + lane * 2) = make_float2(x0 - lse, x1 - lse);
    }
}

// ---------------- launch ----------------
extern "C" void kernel_launch(void* const* d_in, const int* in_sizes, int n_in,
                              void* d_out, int out_size)
{
    const float* x   = (const float*)d_in[0];
    const int*   ei  = (const int*)d_in[1];
    const float* W0  = (const float*)d_in[2];
    const float* as0 = (const float*)d_in[3];
    const float* ad0 = (const float*)d_in[4];
    const float* b0  = (const float*)d_in[5];
    const float* W1  = (const float*)d_in[6];
    const float* as1 = (const float*)d_in[7];
    const float* ad1 = (const float*)d_in[8];
    const float* b1  = (const float*)d_in[9];
    const float* W2  = (const float*)d_in[10];
    const float* as2 = (const float*)d_in[11];
    const float* ad2 = (const float*)d_in[12];
    const float* b2  = (const float*)d_in[13];

    int n = in_sizes[0] / HD;
    int E = in_sizes[1] / 2;
    const int* src = ei;
    const int* dst = ei + E;

    float *h = nullptr, *agg = nullptr;
    uint4 *bf0, *bf1, *bf2;
    cudaGetSymbolAddress((void**)&h, g_h);
    cudaGetSymbolAddress((void**)&agg, g_agg);
    cudaGetSymbolAddress((void**)&bf0, g_bf0);
    cudaGetSymbolAddress((void**)&bf1, g_bf1);
    cudaGetSymbolAddress((void**)&bf2, g_bf2);

    const int smemA = 2 * 128 * 136 * 2;   // 69632 bytes (hi + lo tiles)
    cudaFuncSetAttribute(gemm_mma<128, false>, cudaFuncAttributeMaxDynamicSharedMemorySize, smemA);
    cudaFuncSetAttribute(gemm_mma<128, true>,  cudaFuncAttributeMaxDynamicSharedMemorySize, smemA);
    cudaFuncSetAttribute(gemm_mma<64, true>,   cudaFuncAttributeMaxDynamicSharedMemorySize, smemA);

    wprep_kernel<<<40, 256>>>(W0, W1, W2);

    zero_kernel<<<(n + 255) / 256, 256>>>(n);
    hist_kernel<<<(E / 4 + 255) / 256, 256>>>(dst, E);
    scan_kernel<<<1, 1024>>>(n);
    fill_kernel<<<((E + n + 3) / 4 + 255) / 256, 256>>>(src, dst, E, n);

    int gemmg = (n + 127) / 128;
    int warpg = (n * 32 + 255) / 256;

    gemm_mma<128, false><<<gemmg, 256, smemA>>>(x, bf0, nullptr, as0, ad0, h, n);
    agg_kernel<128, false><<<warpg, 256>>>(h, agg, nullptr, n);

    gemm_mma<128, true><<<gemmg, 256, smemA>>>(agg, bf1, b0, as1, ad1, h, n);
    agg_kernel<128, false><<<warpg, 256>>>(h, agg, nullptr, n);

    gemm_mma<64, true><<<gemmg, 256, smemA>>>(agg, bf2, b1, as2, ad2, h, n);
    agg_kernel<64, true><<<warpg, 256>>>(h, (float*)d_out, b2, n);
}

// round 6
// speedup vs baseline: 1.6213x; 1.3198x over previous
#include <cuda_runtime.h>
#include <cuda_bf16.h>
#include <cstdint>

#define NMAX 50000
#define EMAX 660000
#define HD   128

// ---------------- device scratch ----------------
__device__ __align__(16) float g_h[NMAX * HD];
__device__ __align__(16) float g_agg[NMAX * HD];
__device__ __align__(16) float g_ssrc[NMAX];
__device__ __align__(16) float g_sdst[NMAX];
__device__ __align__(16) int   g_cnt[NMAX];
__device__ __align__(16) int   g_wptr[NMAX];
__device__ __align__(16) int   g_rowptr[NMAX + 1];
__device__ __align__(16) int   g_col[EMAX];
__device__ __align__(16) int   g_bsum[256];
__device__ __align__(16) int   g_boff[256];
// B fragments in mma order: [nb][ks][lane] -> {bhi0, bhi1, blo0, blo1}
__device__ uint4 g_bf0[16 * 8 * 32];
__device__ uint4 g_bf1[16 * 8 * 32];
__device__ uint4 g_bf2[8 * 8 * 32];

__device__ __forceinline__ uint32_t smem_u32(const void* p) {
    uint32_t a;
    asm("{ .reg .u64 t; cvta.to.shared.u64 t, %1; cvt.u32.u64 %0, t; }" : "=r"(a) : "l"(p));
    return a;
}
__device__ __forceinline__ void ldmatrix_x4(uint32_t* r, uint32_t addr) {
    asm volatile("ldmatrix.sync.aligned.m8n8.x4.shared.b16 {%0,%1,%2,%3}, [%4];"
                 : "=r"(r[0]), "=r"(r[1]), "=r"(r[2]), "=r"(r[3]) : "r"(addr));
}
__device__ __forceinline__ void mma16816(float* c, const uint32_t* a, uint32_t b0, uint32_t b1) {
    asm volatile(
        "mma.sync.aligned.m16n8k16.row.col.f32.bf16.bf16.f32 "
        "{%0,%1,%2,%3}, {%4,%5,%6,%7}, {%8,%9}, {%0,%1,%2,%3};"
        : "+f"(c[0]), "+f"(c[1]), "+f"(c[2]), "+f"(c[3])
        : "r"(a[0]), "r"(a[1]), "r"(a[2]), "r"(a[3]), "r"(b0), "r"(b1));
}
__device__ __forceinline__ uint32_t pack_hi(float a, float b) {
    __nv_bfloat162 h = __floats2bfloat162_rn(a, b);
    return *(uint32_t*)&h;
}

// ---------------- CSR build ----------------
__global__ void zero_kernel(int n) {
    int i = blockIdx.x * blockDim.x + threadIdx.x;
    if (i < n) g_cnt[i] = 0;
}
__global__ void hist_kernel(const int* __restrict__ dst, int E) {
    int b = (blockIdx.x * blockDim.x + threadIdx.x) * 4;
    #pragma unroll
    for (int j = 0; j < 4; j++)
        if (b + j < E) atomicAdd(&g_cnt[dst[b + j]], 1);
}

// ---- 3-phase parallel scan over vals[i] = cnt[i] + 1 ----
// block-level exclusive shuffle scan helper (256 threads, 1 item/thread)
__device__ __forceinline__ int block_scan_excl(int val, int tid, int* total) {
    __shared__ int wsum[8];
    int lane = tid & 31, warp = tid >> 5;
    int v = val;
    #pragma unroll
    for (int o = 1; o < 32; o <<= 1) {
        int u = __shfl_up_sync(0xffffffffu, v, o);
        if (lane >= o) v += u;
    }
    if (lane == 31) wsum[warp] = v;
    __syncthreads();
    if (tid < 8) {
        int w = wsum[tid];
        #pragma unroll
        for (int o = 1; o < 8; o <<= 1) {
            int u = __shfl_up_sync(0xffu, w, o);
            if (tid >= o) w += u;
        }
        wsum[tid] = w;
    }
    __syncthreads();
    int excl = v - val + (warp ? wsum[warp - 1] : 0);
    if (total) *total = wsum[7];
    return excl;
}

__global__ __launch_bounds__(256) void scan_reduce(int n) {
    int i = blockIdx.x * 256 + threadIdx.x;
    int val = (i < n) ? (g_cnt[i] + 1) : 0;
    // warp reduce then smem
    #pragma unroll
    for (int o = 16; o; o >>= 1) val += __shfl_xor_sync(0xffffffffu, val, o);
    __shared__ int ws[8];
    if ((threadIdx.x & 31) == 0) ws[threadIdx.x >> 5] = val;
    __syncthreads();
    if (threadIdx.x == 0) {
        int s = 0;
        #pragma unroll
        for (int w = 0; w < 8; w++) s += ws[w];
        g_bsum[blockIdx.x] = s;
    }
}
__global__ __launch_bounds__(256) void scan_bsums(int nb, int n) {
    int tid = threadIdx.x;
    int val = (tid < nb) ? g_bsum[tid] : 0;
    int total;
    int excl = block_scan_excl(val, tid, &total);
    if (tid < nb) g_boff[tid] = excl;
    if (tid == 0) g_rowptr[n] = total;
}
__global__ __launch_bounds__(256) void scan_write(int n) {
    int i = blockIdx.x * 256 + threadIdx.x;
    int val = (i < n) ? (g_cnt[i] + 1) : 0;
    int excl = block_scan_excl(val, threadIdx.x, nullptr);
    if (i < n) {
        int p = g_boff[blockIdx.x] + excl;
        g_rowptr[i] = p;
        g_wptr[i] = p;
    }
}

__global__ void fill_kernel(const int* __restrict__ src, const int* __restrict__ dst,
                            int E, int n) {
    int b = (blockIdx.x * blockDim.x + threadIdx.x) * 4;
    #pragma unroll
    for (int j = 0; j < 4; j++) {
        int i = b + j;
        if (i < E) {
            int p = atomicAdd(&g_wptr[dst[i]], 1);
            g_col[p] = src[i];
        } else if (i < E + n) {
            int vtx = i - E;
            int p = atomicAdd(&g_wptr[vtx], 1);
            g_col[p] = vtx;
        }
    }
}

// ---------------- W prep: pack B fragments (hi/lo bf16 split) ----------------
__global__ void wprep_kernel(const float* __restrict__ W0, const float* __restrict__ W1,
                             const float* __restrict__ W2) {
    int idx = blockIdx.x * blockDim.x + threadIdx.x;
    const float* W;
    uint4* out;
    int N, local;
    if (idx < 4096)       { W = W0; out = g_bf0; N = 128; local = idx; }
    else if (idx < 8192)  { W = W1; out = g_bf1; N = 128; local = idx - 4096; }
    else if (idx < 10240) { W = W2; out = g_bf2; N = 64;  local = idx - 8192; }
    else return;
    int lane = local & 31;
    int ks = (local >> 5) & 7;
    int nb = local >> 8;
    int g = lane >> 2, t = lane & 3;
    int nn = nb * 8 + g;
    int k0 = ks * 16 + t * 2;
    float w00 = W[(k0 + 0) * N + nn], w01 = W[(k0 + 1) * N + nn];
    float w10 = W[(k0 + 8) * N + nn], w11 = W[(k0 + 9) * N + nn];
    __nv_bfloat16 h00 = __float2bfloat16(w00), h01 = __float2bfloat16(w01);
    __nv_bfloat16 h10 = __float2bfloat16(w10), h11 = __float2bfloat16(w11);
    uint4 o;
    o.x = pack_hi(w00, w01);
    o.y = pack_hi(w10, w11);
    o.z = pack_hi(w00 - __bfloat162float(h00), w01 - __bfloat162float(h01));
    o.w = pack_hi(w10 - __bfloat162float(h10), w11 - __bfloat162float(h11));
    out[local] = o;
}

// ---------------- bf16 mma GEMM + fused attention-score epilogue ----------------
__device__ __forceinline__ float silu(float v) { return v / (1.0f + __expf(-v)); }

template<int DOUT, bool ACT>
__global__ __launch_bounds__(256) void gemm_mma(
    const float* __restrict__ X, const uint4* __restrict__ Bf,
    const float* __restrict__ bin,
    const float* __restrict__ av_s, const float* __restrict__ av_d,
    float* __restrict__ O, int n)
{
    constexpr int NSTEP = DOUT / 8;
    constexpr int AST = 136;
    extern __shared__ __align__(16) char smem[];
    __nv_bfloat16* Ahi = (__nv_bfloat16*)smem;
    __nv_bfloat16* Alo = Ahi + 128 * AST;

    const int tid = threadIdx.x;
    const int wid = tid >> 5;
    const int lane = tid & 31;
    const int row0 = blockIdx.x * 128;

    for (int i = tid; i < 4096; i += 256) {
        int row = i >> 5, c4 = (i & 31) * 4;
        float4 v = make_float4(0.f, 0.f, 0.f, 0.f);
        if (row0 + row < n) v = *(const float4*)(X + (size_t)(row0 + row) * HD + c4);
        if (ACT) {
            v.x = silu(v.x + bin[c4 + 0]);
            v.y = silu(v.y + bin[c4 + 1]);
            v.z = silu(v.z + bin[c4 + 2]);
            v.w = silu(v.w + bin[c4 + 3]);
        }
        __nv_bfloat162 h01 = __floats2bfloat162_rn(v.x, v.y);
        __nv_bfloat162 h23 = __floats2bfloat162_rn(v.z, v.w);
        __nv_bfloat162 l01 = __floats2bfloat162_rn(v.x - __low2float(h01), v.y - __high2float(h01));
        __nv_bfloat162 l23 = __floats2bfloat162_rn(v.z - __low2float(h23), v.w - __high2float(h23));
        *(__nv_bfloat162*)(Ahi + row * AST + c4)     = h01;
        *(__nv_bfloat162*)(Ahi + row * AST + c4 + 2) = h23;
        *(__nv_bfloat162*)(Alo + row * AST + c4)     = l01;
        *(__nv_bfloat162*)(Alo + row * AST + c4 + 2) = l23;
    }
    __syncthreads();

    float acc[NSTEP][4];
    #pragma unroll
    for (int i = 0; i < NSTEP; i++) {
        acc[i][0] = acc[i][1] = acc[i][2] = acc[i][3] = 0.f;
    }

    const int arow = 16 * wid + (lane & 15);
    const int acol = (lane >> 4) * 8;
    const uint32_t ahi_base = smem_u32(Ahi + arow * AST + acol);
    const uint32_t alo_base = smem_u32(Alo + arow * AST + acol);

    #pragma unroll
    for (int ks = 0; ks < 8; ks++) {
        uint32_t ahi[4], alo[4];
        ldmatrix_x4(ahi, ahi_base + ks * 32);
        ldmatrix_x4(alo, alo_base + ks * 32);
        #pragma unroll
        for (int nb = 0; nb < NSTEP; nb++) {
            uint4 b = __ldg(&Bf[(nb * 8 + ks) * 32 + lane]);
            mma16816(acc[nb], ahi, b.x, b.y);
            mma16816(acc[nb], ahi, b.z, b.w);
            mma16816(acc[nb], alo, b.x, b.y);
        }
    }

    const int g = lane >> 2, t = lane & 3;
    const int r0 = row0 + 16 * wid + g;
    const int r1 = r0 + 8;
    float ss0 = 0.f, sd0 = 0.f, ss1 = 0.f, sd1 = 0.f;
    #pragma unroll
    for (int nb = 0; nb < NSTEP; nb++) {
        int c = nb * 8 + t * 2;
        float a0 = __ldg(&av_s[c]), a1 = __ldg(&av_s[c + 1]);
        float d0 = __ldg(&av_d[c]), d1 = __ldg(&av_d[c + 1]);
        ss0 += acc[nb][0] * a0 + acc[nb][1] * a1;
        sd0 += acc[nb][0] * d0 + acc[nb][1] * d1;
        ss1 += acc[nb][2] * a0 + acc[nb][3] * a1;
        sd1 += acc[nb][2] * d0 + acc[nb][3] * d1;
        if (r0 < n) *(float2*)(O + (size_t)r0 * DOUT + c) = make_float2(acc[nb][0], acc[nb][1]);
        if (r1 < n) *(float2*)(O + (size_t)r1 * DOUT + c) = make_float2(acc[nb][2], acc[nb][3]);
    }
    #pragma unroll
    for (int o = 1; o <= 2; o <<= 1) {
        ss0 += __shfl_xor_sync(0xffffffffu, ss0, o);
        sd0 += __shfl_xor_sync(0xffffffffu, sd0, o);
        ss1 += __shfl_xor_sync(0xffffffffu, ss1, o);
        sd1 += __shfl_xor_sync(0xffffffffu, sd1, o);
    }
    if (t == 0) {
        if (r0 < n) { g_ssrc[r0] = ss0; g_sdst[r0] = sd0; }
        if (r1 < n) { g_ssrc[r1] = ss1; g_sdst[r1] = sd1; }
    }
}

// ---------------- aggregation (warp per destination node) ----------------
template<int DOUT, bool FINAL>
__global__ __launch_bounds__(256) void agg_kernel(const float* __restrict__ Hin,
    float* __restrict__ out, const float* __restrict__ bias, int n)
{
    int gw = (blockIdx.x * blockDim.x + threadIdx.x) >> 5;
    int lane = threadIdx.x & 31;
    if (gw >= n) return;
    int beg = g_rowptr[gw], end = g_rowptr[gw + 1];
    float sd = g_sdst[gw];

    float m = -1e30f;
    for (int j = beg + lane; j < end; j += 32) {
        float v = g_ssrc[g_col[j]] + sd;
        v = v > 0.f ? v : 0.2f * v;
        m = fmaxf(m, v);
    }
    #pragma unroll
    for (int o = 16; o; o >>= 1) m = fmaxf(m, __shfl_xor_sync(0xffffffffu, m, o));

    constexpr int V = DOUT / 32;
    float acc[V];
    #pragma unroll
    for (int t = 0; t < V; t++) acc[t] = 0.f;
    float denom = 0.f;
    int j = beg;
    for (; j + 1 < end; j += 2) {
        int s0 = g_col[j], s1 = g_col[j + 1];
        float v0 = g_ssrc[s0] + sd, v1 = g_ssrc[s1] + sd;
        v0 = v0 > 0.f ? v0 : 0.2f * v0;
        v1 = v1 > 0.f ? v1 : 0.2f * v1;
        float e0 = __expf(v0 - m), e1 = __expf(v1 - m);
        denom += e0 + e1;
        if constexpr (V == 4) {
            float4 h0 = *(const float4*)(Hin + (size_t)s0 * DOUT + lane * 4);
            float4 h1 = *(const float4*)(Hin + (size_t)s1 * DOUT + lane * 4);
            acc[0] += e0 * h0.x + e1 * h1.x;
            acc[1] += e0 * h0.y + e1 * h1.y;
            acc[2] += e0 * h0.z + e1 * h1.z;
            acc[3] += e0 * h0.w + e1 * h1.w;
        } else {
            float2 h0 = *(const float2*)(Hin + (size_t)s0 * DOUT + lane * 2);
            float2 h1 = *(const float2*)(Hin + (size_t)s1 * DOUT + lane * 2);
            acc[0] += e0 * h0.x + e1 * h1.x;
            acc[1] += e0 * h0.y + e1 * h1.y;
        }
    }
    if (j < end) {
        int s0 = g_col[j];
        float v0 = g_ssrc[s0] + sd;
        v0 = v0 > 0.f ? v0 : 0.2f * v0;
        float e0 = __expf(v0 - m);
        denom += e0;
        if constexpr (V == 4) {
            float4 h0 = *(const float4*)(Hin + (size_t)s0 * DOUT + lane * 4);
            acc[0] += e0 * h0.x; acc[1] += e0 * h0.y;
            acc[2] += e0 * h0.z; acc[3] += e0 * h0.w;
        } else {
            float2 h0 = *(const float2*)(Hin + (size_t)s0 * DOUT + lane * 2);
            acc[0] += e0 * h0.x; acc[1] += e0 * h0.y;
        }
    }
    float inv = 1.0f / denom;

    if constexpr (!FINAL) {
        if constexpr (V == 4) {
            *(float4*)(out + (size_t)gw * DOUT + lane * 4) =
                make_float4(acc[0] * inv, acc[1] * inv, acc[2] * inv, acc[3] * inv);
        } else {
            *(float2*)(out + (size_t)gw * DOUT + lane * 2) =
                make_float2(acc[0] * inv, acc[1] * inv);
        }
    } else {
        float2 bb = *(const float2*)(bias + lane * 2);
        float x0 = acc[0] * inv + bb.x;
        float x1 = acc[1] * inv + bb.y;
        float mm = fmaxf(x0, x1);
        #pragma unroll
        for (int o = 16; o; o >>= 1) mm = fmaxf(mm, __shfl_xor_sync(0xffffffffu, mm, o));
        float s = __expf(x0 - mm) + __expf(x1 - mm);
        #pragma unroll
        for (int o = 16; o; o >>= 1) s += __shfl_xor_sync(0xffffffffu, s, o);
        float lse = mm + __logf(s);
        *(float2*)(out + (size_t)gw * 64 + lane * 2) = make_float2(x0 - lse, x1 - lse);
    }
}

// ---------------- launch ----------------
extern "C" void kernel_launch(void* const* d_in, const int* in_sizes, int n_in,
                              void* d_out, int out_size)
{
    const float* x   = (const float*)d_in[0];
    const int*   ei  = (const int*)d_in[1];
    const float* W0  = (const float*)d_in[2];
    const float* as0 = (const float*)d_in[3];
    const float* ad0 = (const float*)d_in[4];
    const float* b0  = (const float*)d_in[5];
    const float* W1  = (const float*)d_in[6];
    const float* as1 = (const float*)d_in[7];
    const float* ad1 = (const float*)d_in[8];
    const float* b1  = (const float*)d_in[9];
    const float* W2  = (const float*)d_in[10];
    const float* as2 = (const float*)d_in[11];
    const float* ad2 = (const float*)d_in[12];
    const float* b2  = (const float*)d_in[13];

    int n = in_sizes[0] / HD;
    int E = in_sizes[1] / 2;
    const int* src = ei;
    const int* dst = ei + E;

    float *h = nullptr, *agg = nullptr;
    uint4 *bf0, *bf1, *bf2;
    cudaGetSymbolAddress((void**)&h, g_h);
    cudaGetSymbolAddress((void**)&agg, g_agg);
    cudaGetSymbolAddress((void**)&bf0, g_bf0);
    cudaGetSymbolAddress((void**)&bf1, g_bf1);
    cudaGetSymbolAddress((void**)&bf2, g_bf2);

    const int smemA = 2 * 128 * 136 * 2;   // 69632 bytes
    cudaFuncSetAttribute(gemm_mma<128, false>, cudaFuncAttributeMaxDynamicSharedMemorySize, smemA);
    cudaFuncSetAttribute(gemm_mma<128, true>,  cudaFuncAttributeMaxDynamicSharedMemorySize, smemA);
    cudaFuncSetAttribute(gemm_mma<64, true>,   cudaFuncAttributeMaxDynamicSharedMemorySize, smemA);

    wprep_kernel<<<40, 256>>>(W0, W1, W2);

    int nb = (n + 255) / 256;   // 196 blocks
    zero_kernel<<<(n + 255) / 256, 256>>>(n);
    hist_kernel<<<(E / 4 + 255) / 256, 256>>>(dst, E);
    scan_reduce<<<nb, 256>>>(n);
    scan_bsums<<<1, 256>>>(nb, n);
    scan_write<<<nb, 256>>>(n);
    fill_kernel<<<((E + n + 3) / 4 + 255) / 256, 256>>>(src, dst, E, n);

    int gemmg = (n + 127) / 128;
    int warpg = (n * 32 + 255) / 256;

    gemm_mma<128, false><<<gemmg, 256, smemA>>>(x, bf0, nullptr, as0, ad0, h, n);
    agg_kernel<128, false><<<warpg, 256>>>(h, agg, nullptr, n);

    gemm_mma<128, true><<<gemmg, 256, smemA>>>(agg, bf1, b0, as1, ad1, h, n);
    agg_kernel<128, false><<<warpg, 256>>>(h, agg, nullptr, n);

    gemm_mma<64, true><<<gemmg, 256, smemA>>>(agg, bf2, b1, as2, ad2, h, n);
    agg_kernel<64, true><<<warpg, 256>>>(h, (float*)d_out, b2, n);
}

// round 8
// speedup vs baseline: 1.6514x; 1.0186x over previous
#include <cuda_runtime.h>
#include <cuda_bf16.h>
#include <cstdint>

#define NMAX 50000
#define EMAX 660000
#define HD   128

// ---------------- device scratch ----------------
__device__ __align__(16) float g_h[NMAX * HD];
__device__ __align__(16) float g_agg[NMAX * HD];
__device__ __align__(16) float g_ssrc[NMAX];
__device__ __align__(16) float g_sdst[NMAX];
__device__ __align__(16) int   g_cnt[NMAX];
__device__ __align__(16) int   g_wptr[NMAX];
__device__ __align__(16) int   g_rowptr[NMAX + 1];
__device__ __align__(16) int   g_col[EMAX];
__device__ __align__(16) int   g_bsum[256];
__device__ __align__(16) int   g_boff[256];
// B fragments in mma order: [nb][ks][lane] -> {bhi0, bhi1, blo0, blo1}
__device__ uint4 g_bf0[16 * 8 * 32];
__device__ uint4 g_bf1[16 * 8 * 32];
__device__ uint4 g_bf2[8 * 8 * 32];

__device__ __forceinline__ uint32_t smem_u32(const void* p) {
    uint32_t a;
    asm("{ .reg .u64 t; cvta.to.shared.u64 t, %1; cvt.u32.u64 %0, t; }" : "=r"(a) : "l"(p));
    return a;
}
__device__ __forceinline__ void ldmatrix_x4(uint32_t* r, uint32_t addr) {
    asm volatile("ldmatrix.sync.aligned.m8n8.x4.shared.b16 {%0,%1,%2,%3}, [%4];"
                 : "=r"(r[0]), "=r"(r[1]), "=r"(r[2]), "=r"(r[3]) : "r"(addr));
}
__device__ __forceinline__ void mma16816(float* c, const uint32_t* a, uint32_t b0, uint32_t b1) {
    asm volatile(
        "mma.sync.aligned.m16n8k16.row.col.f32.bf16.bf16.f32 "
        "{%0,%1,%2,%3}, {%4,%5,%6,%7}, {%8,%9}, {%0,%1,%2,%3};"
        : "+f"(c[0]), "+f"(c[1]), "+f"(c[2]), "+f"(c[3])
        : "r"(a[0]), "r"(a[1]), "r"(a[2]), "r"(a[3]), "r"(b0), "r"(b1));
}
__device__ __forceinline__ uint32_t pack_hi(float a, float b) {
    __nv_bfloat162 h = __floats2bfloat162_rn(a, b);
    return *(uint32_t*)&h;
}

// ---------------- CSR build ----------------
__global__ void zero_kernel(int n) {
    int i = blockIdx.x * blockDim.x + threadIdx.x;
    if (i < n) g_cnt[i] = 0;
}
__global__ void hist_kernel(const int* __restrict__ dst, int E) {
    int b = (blockIdx.x * blockDim.x + threadIdx.x) * 4;
    #pragma unroll
    for (int j = 0; j < 4; j++)
        if (b + j < E) atomicAdd(&g_cnt[dst[b + j]], 1);
}

// ---- 3-phase parallel scan over vals[i] = cnt[i] + 1 ----
__device__ __forceinline__ int block_scan_excl(int val, int tid, int* total) {
    __shared__ int wsum[8];
    int lane = tid & 31, warp = tid >> 5;
    int v = val;
    #pragma unroll
    for (int o = 1; o < 32; o <<= 1) {
        int u = __shfl_up_sync(0xffffffffu, v, o);
        if (lane >= o) v += u;
    }
    if (lane == 31) wsum[warp] = v;
    __syncthreads();
    if (tid < 8) {
        int w = wsum[tid];
        #pragma unroll
        for (int o = 1; o < 8; o <<= 1) {
            int u = __shfl_up_sync(0xffu, w, o);
            if (tid >= o) w += u;
        }
        wsum[tid] = w;
    }
    __syncthreads();
    int excl = v - val + (warp ? wsum[warp - 1] : 0);
    if (total) *total = wsum[7];
    return excl;
}

__global__ __launch_bounds__(256) void scan_reduce(int n) {
    int i = blockIdx.x * 256 + threadIdx.x;
    int val = (i < n) ? (g_cnt[i] + 1) : 0;
    #pragma unroll
    for (int o = 16; o; o >>= 1) val += __shfl_xor_sync(0xffffffffu, val, o);
    __shared__ int ws[8];
    if ((threadIdx.x & 31) == 0) ws[threadIdx.x >> 5] = val;
    __syncthreads();
    if (threadIdx.x == 0) {
        int s = 0;
        #pragma unroll
        for (int w = 0; w < 8; w++) s += ws[w];
        g_bsum[blockIdx.x] = s;
    }
}
__global__ __launch_bounds__(256) void scan_bsums(int nb, int n) {
    int tid = threadIdx.x;
    int val = (tid < nb) ? g_bsum[tid] : 0;
    int total;
    int excl = block_scan_excl(val, tid, &total);
    if (tid < nb) g_boff[tid] = excl;
    if (tid == 0) g_rowptr[n] = total;
}
__global__ __launch_bounds__(256) void scan_write(int n) {
    int i = blockIdx.x * 256 + threadIdx.x;
    int val = (i < n) ? (g_cnt[i] + 1) : 0;
    int excl = block_scan_excl(val, threadIdx.x, nullptr);
    if (i < n) {
        int p = g_boff[blockIdx.x] + excl;
        g_rowptr[i] = p;
        g_wptr[i] = p;
    }
}

__global__ void fill_kernel(const int* __restrict__ src, const int* __restrict__ dst,
                            int E, int n) {
    int b = (blockIdx.x * blockDim.x + threadIdx.x) * 4;
    #pragma unroll
    for (int j = 0; j < 4; j++) {
        int i = b + j;
        if (i < E) {
            int p = atomicAdd(&g_wptr[dst[i]], 1);
            g_col[p] = src[i];
        } else if (i < E + n) {
            int vtx = i - E;
            int p = atomicAdd(&g_wptr[vtx], 1);
            g_col[p] = vtx;
        }
    }
}

// ---------------- W prep: pack B fragments (hi/lo bf16 split) ----------------
__global__ void wprep_kernel(const float* __restrict__ W0, const float* __restrict__ W1,
                             const float* __restrict__ W2) {
    int idx = blockIdx.x * blockDim.x + threadIdx.x;
    const float* W;
    uint4* out;
    int N, local;
    if (idx < 4096)       { W = W0; out = g_bf0; N = 128; local = idx; }
    else if (idx < 8192)  { W = W1; out = g_bf1; N = 128; local = idx - 4096; }
    else if (idx < 10240) { W = W2; out = g_bf2; N = 64;  local = idx - 8192; }
    else return;
    int lane = local & 31;
    int ks = (local >> 5) & 7;
    int nb = local >> 8;
    int g = lane >> 2, t = lane & 3;
    int nn = nb * 8 + g;
    int k0 = ks * 16 + t * 2;
    float w00 = W[(k0 + 0) * N + nn], w01 = W[(k0 + 1) * N + nn];
    float w10 = W[(k0 + 8) * N + nn], w11 = W[(k0 + 9) * N + nn];
    __nv_bfloat16 h00 = __float2bfloat16(w00), h01 = __float2bfloat16(w01);
    __nv_bfloat16 h10 = __float2bfloat16(w10), h11 = __float2bfloat16(w11);
    uint4 o;
    o.x = pack_hi(w00, w01);
    o.y = pack_hi(w10, w11);
    o.z = pack_hi(w00 - __bfloat162float(h00), w01 - __bfloat162float(h01));
    o.w = pack_hi(w10 - __bfloat162float(h10), w11 - __bfloat162float(h11));
    out[local] = o;
}

// ---------------- bf16 mma GEMM + fused attention-score epilogue ----------------
__device__ __forceinline__ float silu(float v) { return v / (1.0f + __expf(-v)); }

template<int DOUT, bool ACT>
__global__ __launch_bounds__(256) void gemm_mma(
    const float* __restrict__ X, const uint4* __restrict__ Bf,
    const float* __restrict__ bin,
    const float* __restrict__ av_s, const float* __restrict__ av_d,
    float* __restrict__ O, int n)
{
    constexpr int NSTEP = DOUT / 8;
    constexpr int AST = 136;
    extern __shared__ __align__(16) char smem[];
    __nv_bfloat16* Ahi = (__nv_bfloat16*)smem;
    __nv_bfloat16* Alo = Ahi + 128 * AST;

    const int tid = threadIdx.x;
    const int wid = tid >> 5;
    const int lane = tid & 31;
    const int row0 = blockIdx.x * 128;

    for (int i = tid; i < 4096; i += 256) {
        int row = i >> 5, c4 = (i & 31) * 4;
        float4 v = make_float4(0.f, 0.f, 0.f, 0.f);
        if (row0 + row < n) v = *(const float4*)(X + (size_t)(row0 + row) * HD + c4);
        if (ACT) {
            v.x = silu(v.x + bin[c4 + 0]);
            v.y = silu(v.y + bin[c4 + 1]);
            v.z = silu(v.z + bin[c4 + 2]);
            v.w = silu(v.w + bin[c4 + 3]);
        }
        __nv_bfloat162 h01 = __floats2bfloat162_rn(v.x, v.y);
        __nv_bfloat162 h23 = __floats2bfloat162_rn(v.z, v.w);
        __nv_bfloat162 l01 = __floats2bfloat162_rn(v.x - __low2float(h01), v.y - __high2float(h01));
        __nv_bfloat162 l23 = __floats2bfloat162_rn(v.z - __low2float(h23), v.w - __high2float(h23));
        *(__nv_bfloat162*)(Ahi + row * AST + c4)     = h01;
        *(__nv_bfloat162*)(Ahi + row * AST + c4 + 2) = h23;
        *(__nv_bfloat162*)(Alo + row * AST + c4)     = l01;
        *(__nv_bfloat162*)(Alo + row * AST + c4 + 2) = l23;
    }
    __syncthreads();

    float acc[NSTEP][4];
    #pragma unroll
    for (int i = 0; i < NSTEP; i++) {
        acc[i][0] = acc[i][1] = acc[i][2] = acc[i][3] = 0.f;
    }

    const int arow = 16 * wid + (lane & 15);
    const int acol = (lane >> 4) * 8;
    const uint32_t ahi_base = smem_u32(Ahi + arow * AST + acol);
    const uint32_t alo_base = smem_u32(Alo + arow * AST + acol);

    #pragma unroll
    for (int ks = 0; ks < 8; ks++) {
        uint32_t ahi[4], alo[4];
        ldmatrix_x4(ahi, ahi_base + ks * 32);
        ldmatrix_x4(alo, alo_base + ks * 32);
        #pragma unroll
        for (int nb = 0; nb < NSTEP; nb++) {
            uint4 b = __ldg(&Bf[(nb * 8 + ks) * 32 + lane]);
            mma16816(acc[nb], ahi, b.x, b.y);
            mma16816(acc[nb], ahi, b.z, b.w);
            mma16816(acc[nb], alo, b.x, b.y);
        }
    }

    const int g = lane >> 2, t = lane & 3;
    const int r0 = row0 + 16 * wid + g;
    const int r1 = r0 + 8;
    float ss0 = 0.f, sd0 = 0.f, ss1 = 0.f, sd1 = 0.f;
    #pragma unroll
    for (int nb = 0; nb < NSTEP; nb++) {
        int c = nb * 8 + t * 2;
        float a0 = __ldg(&av_s[c]), a1 = __ldg(&av_s[c + 1]);
        float d0 = __ldg(&av_d[c]), d1 = __ldg(&av_d[c + 1]);
        ss0 += acc[nb][0] * a0 + acc[nb][1] * a1;
        sd0 += acc[nb][0] * d0 + acc[nb][1] * d1;
        ss1 += acc[nb][2] * a0 + acc[nb][3] * a1;
        sd1 += acc[nb][2] * d0 + acc[nb][3] * d1;
        if (r0 < n) *(float2*)(O + (size_t)r0 * DOUT + c) = make_float2(acc[nb][0], acc[nb][1]);
        if (r1 < n) *(float2*)(O + (size_t)r1 * DOUT + c) = make_float2(acc[nb][2], acc[nb][3]);
    }
    #pragma unroll
    for (int o = 1; o <= 2; o <<= 1) {
        ss0 += __shfl_xor_sync(0xffffffffu, ss0, o);
        sd0 += __shfl_xor_sync(0xffffffffu, sd0, o);
        ss1 += __shfl_xor_sync(0xffffffffu, ss1, o);
        sd1 += __shfl_xor_sync(0xffffffffu, sd1, o);
    }
    if (t == 0) {
        if (r0 < n) { g_ssrc[r0] = ss0; g_sdst[r0] = sd0; }
        if (r1 < n) { g_ssrc[r1] = ss1; g_sdst[r1] = sd1; }
    }
}

// ---------------- aggregation: single pass, self-loop score as stabilizer ----------------
template<int DOUT, bool FINAL>
__global__ __launch_bounds__(256) void agg_kernel(const float* __restrict__ Hin,
    float* __restrict__ out, const float* __restrict__ bias, int n)
{
    int gw = (blockIdx.x * blockDim.x + threadIdx.x) >> 5;
    int lane = threadIdx.x & 31;
    if (gw >= n) return;
    int beg = g_rowptr[gw], end = g_rowptr[gw + 1];
    float sd = g_sdst[gw];

    // stabilizer: this node's self-loop score (always in the neighborhood)
    float m = g_ssrc[gw] + sd;
    m = m > 0.f ? m : 0.2f * m;

    constexpr int V = DOUT / 32;
    float acc[V];
    #pragma unroll
    for (int t = 0; t < V; t++) acc[t] = 0.f;
    float denom = 0.f;
    int j = beg;
    for (; j + 1 < end; j += 2) {
        int s0 = g_col[j], s1 = g_col[j + 1];
        float v0 = g_ssrc[s0] + sd, v1 = g_ssrc[s1] + sd;
        v0 = v0 > 0.f ? v0 : 0.2f * v0;
        v1 = v1 > 0.f ? v1 : 0.2f * v1;
        float e0 = __expf(v0 - m), e1 = __expf(v1 - m);
        denom += e0 + e1;
        if constexpr (V == 4) {
            float4 h0 = *(const float4*)(Hin + (size_t)s0 * DOUT + lane * 4);
            float4 h1 = *(const float4*)(Hin + (size_t)s1 * DOUT + lane * 4);
            acc[0] += e0 * h0.x + e1 * h1.x;
            acc[1] += e0 * h0.y + e1 * h1.y;
            acc[2] += e0 * h0.z + e1 * h1.z;
            acc[3] += e0 * h0.w + e1 * h1.w;
        } else {
            float2 h0 = *(const float2*)(Hin + (size_t)s0 * DOUT + lane * 2);
            float2 h1 = *(const float2*)(Hin + (size_t)s1 * DOUT + lane * 2);
            acc[0] += e0 * h0.x + e1 * h1.x;
            acc[1] += e0 * h0.y + e1 * h1.y;
        }
    }
    if (j < end) {
        int s0 = g_col[j];
        float v0 = g_ssrc[s0] + sd;
        v0 = v0 > 0.f ? v0 : 0.2f * v0;
        float e0 = __expf(v0 - m);
        denom += e0;
        if constexpr (V == 4) {
            float4 h0 = *(const float4*)(Hin + (size_t)s0 * DOUT + lane * 4);
            acc[0] += e0 * h0.x; acc[1] += e0 * h0.y;
            acc[2] += e0 * h0.z; acc[3] += e0 * h0.w;
        } else {
            float2 h0 = *(const float2*)(Hin + (size_t)s0 * DOUT + lane * 2);
            acc[0] += e0 * h0.x; acc[1] += e0 * h0.y;
        }
    }
    float inv = 1.0f / denom;

    if constexpr (!FINAL) {
        if constexpr (V == 4) {
            *(float4*)(out + (size_t)gw * DOUT + lane * 4) =
                make_float4(acc[0] * inv, acc[1] * inv, acc[2] * inv, acc[3] * inv);
        } else {
            *(float2*)(out + (size_t)gw * DOUT + lane * 2) =
                make_float2(acc[0] * inv, acc[1] * inv);
        }
    } else {
        float2 bb = *(const float2*)(bias + lane * 2);
        float x0 = acc[0] * inv + bb.x;
        float x1 = acc[1] * inv + bb.y;
        float mm = fmaxf(x0, x1);
        #pragma unroll
        for (int o = 16; o; o >>= 1) mm = fmaxf(mm, __shfl_xor_sync(0xffffffffu, mm, o));
        float s = __expf(x0 - mm) + __expf(x1 - mm);
        #pragma unroll
        for (int o = 16; o; o >>= 1) s += __shfl_xor_sync(0xffffffffu, s, o);
        float lse = mm + __logf(s);
        *(float2*)(out + (size_t)gw * 64 + lane * 2) = make_float2(x0 - lse, x1 - lse);
    }
}

// ---------------- launch ----------------
extern "C" void kernel_launch(void* const* d_in, const int* in_sizes, int n_in,
                              void* d_out, int out_size)
{
    const float* x   = (const float*)d_in[0];
    const int*   ei  = (const int*)d_in[1];
    const float* W0  = (const float*)d_in[2];
    const float* as0 = (const float*)d_in[3];
    const float* ad0 = (const float*)d_in[4];
    const float* b0  = (const float*)d_in[5];
    const float* W1  = (const float*)d_in[6];
    const float* as1 = (const float*)d_in[7];
    const float* ad1 = (const float*)d_in[8];
    const float* b1  = (const float*)d_in[9];
    const float* W2  = (const float*)d_in[10];
    const float* as2 = (const float*)d_in[11];
    const float* ad2 = (const float*)d_in[12];
    const float* b2  = (const float*)d_in[13];

    int n = in_sizes[0] / HD;
    int E = in_sizes[1] / 2;
    const int* src = ei;
    const int* dst = ei + E;

    float *h = nullptr, *agg = nullptr;
    uint4 *bf0, *bf1, *bf2;
    cudaGetSymbolAddress((void**)&h, g_h);
    cudaGetSymbolAddress((void**)&agg, g_agg);
    cudaGetSymbolAddress((void**)&bf0, g_bf0);
    cudaGetSymbolAddress((void**)&bf1, g_bf1);
    cudaGetSymbolAddress((void**)&bf2, g_bf2);

    const int smemA = 2 * 128 * 136 * 2;   // 69632 bytes
    cudaFuncSetAttribute(gemm_mma<128, false>, cudaFuncAttributeMaxDynamicSharedMemorySize, smemA);
    cudaFuncSetAttribute(gemm_mma<128, true>,  cudaFuncAttributeMaxDynamicSharedMemorySize, smemA);
    cudaFuncSetAttribute(gemm_mma<64, true>,   cudaFuncAttributeMaxDynamicSharedMemorySize, smemA);

    wprep_kernel<<<40, 256>>>(W0, W1, W2);

    int nb = (n + 255) / 256;
    zero_kernel<<<(n + 255) / 256, 256>>>(n);
    hist_kernel<<<(E / 4 + 255) / 256, 256>>>(dst, E);
    scan_reduce<<<nb, 256>>>(n);
    scan_bsums<<<1, 256>>>(nb, n);
    scan_write<<<nb, 256>>>(n);
    fill_kernel<<<((E + n + 3) / 4 + 255) / 256, 256>>>(src, dst, E, n);

    int gemmg = (n + 127) / 128;
    int warpg = (n * 32 + 255) / 256;

    gemm_mma<128, false><<<gemmg, 256, smemA>>>(x, bf0, nullptr, as0, ad0, h, n);
    agg_kernel<128, false><<<warpg, 256>>>(h, agg, nullptr, n);

    gemm_mma<128, true><<<gemmg, 256, smemA>>>(agg, bf1, b0, as1, ad1, h, n);
    agg_kernel<128, false><<<warpg, 256>>>(h, agg, nullptr, n);

    gemm_mma<64, true><<<gemmg, 256, smemA>>>(agg, bf2, b1, as2, ad2, h, n);
    agg_kernel<64, true><<<warpg, 256>>>(h, (float*)d_out, b2, n);
}

// round 11
// speedup vs baseline: 1.6569x; 1.0033x over previous
#include <cuda_runtime.h>
#include <cuda_bf16.h>
#include <cstdint>

#define NMAX 50000
#define EMAX 660000
#define HD   128

// ---------------- device scratch ----------------
__device__ __align__(16) float g_h[NMAX * HD];
__device__ __align__(16) float g_agg[NMAX * HD];
__device__ __align__(16) float g_ssrc[NMAX];
__device__ __align__(16) float g_sdst[NMAX];
__device__ __align__(16) int   g_cnt[NMAX];
__device__ __align__(16) int   g_wptr[NMAX];
__device__ __align__(16) int   g_rowptr[NMAX + 1];
__device__ __align__(16) int   g_col[EMAX];
__device__ __align__(16) int   g_bsum[256];
__device__ __align__(16) int   g_boff[256];
// B fragments in mma order: [nb][ks][lane] -> {bhi0, bhi1, blo0, blo1}
__device__ uint4 g_bf0[16 * 8 * 32];
__device__ uint4 g_bf1[16 * 8 * 32];
__device__ uint4 g_bf2[8 * 8 * 32];

__device__ __forceinline__ uint32_t smem_u32(const void* p) {
    uint32_t a;
    asm("{ .reg .u64 t; cvta.to.shared.u64 t, %1; cvt.u32.u64 %0, t; }" : "=r"(a) : "l"(p));
    return a;
}
__device__ __forceinline__ void ldmatrix_x4(uint32_t* r, uint32_t addr) {
    asm volatile("ldmatrix.sync.aligned.m8n8.x4.shared.b16 {%0,%1,%2,%3}, [%4];"
                 : "=r"(r[0]), "=r"(r[1]), "=r"(r[2]), "=r"(r[3]) : "r"(addr));
}
__device__ __forceinline__ void mma16816(float* c, const uint32_t* a, uint32_t b0, uint32_t b1) {
    asm volatile(
        "mma.sync.aligned.m16n8k16.row.col.f32.bf16.bf16.f32 "
        "{%0,%1,%2,%3}, {%4,%5,%6,%7}, {%8,%9}, {%0,%1,%2,%3};"
        : "+f"(c[0]), "+f"(c[1]), "+f"(c[2]), "+f"(c[3])
        : "r"(a[0]), "r"(a[1]), "r"(a[2]), "r"(a[3]), "r"(b0), "r"(b1));
}
__device__ __forceinline__ uint32_t pack_hi(float a, float b) {
    __nv_bfloat162 h = __floats2bfloat162_rn(a, b);
    return *(uint32_t*)&h;
}

// ---------------- CSR build ----------------
__global__ void zero_kernel(int n) {
    int i = blockIdx.x * blockDim.x + threadIdx.x;
    if (i < n) g_cnt[i] = 0;
}
__global__ void hist_kernel(const int* __restrict__ dst, int E) {
    int b = (blockIdx.x * blockDim.x + threadIdx.x) * 4;
    #pragma unroll
    for (int j = 0; j < 4; j++)
        if (b + j < E) atomicAdd(&g_cnt[dst[b + j]], 1);
}

// ---- 3-phase parallel scan over vals[i] = cnt[i] + 1 ----
__device__ __forceinline__ int block_scan_excl(int val, int tid, int* total) {
    __shared__ int wsum[8];
    int lane = tid & 31, warp = tid >> 5;
    int v = val;
    #pragma unroll
    for (int o = 1; o < 32; o <<= 1) {
        int u = __shfl_up_sync(0xffffffffu, v, o);
        if (lane >= o) v += u;
    }
    if (lane == 31) wsum[warp] = v;
    __syncthreads();
    if (tid < 8) {
        int w = wsum[tid];
        #pragma unroll
        for (int o = 1; o < 8; o <<= 1) {
            int u = __shfl_up_sync(0xffu, w, o);
            if (tid >= o) w += u;
        }
        wsum[tid] = w;
    }
    __syncthreads();
    int excl = v - val + (warp ? wsum[warp - 1] : 0);
    if (total) *total = wsum[7];
    return excl;
}

__global__ __launch_bounds__(256) void scan_reduce(int n) {
    int i = blockIdx.x * 256 + threadIdx.x;
    int val = (i < n) ? (g_cnt[i] + 1) : 0;
    #pragma unroll
    for (int o = 16; o; o >>= 1) val += __shfl_xor_sync(0xffffffffu, val, o);
    __shared__ int ws[8];
    if ((threadIdx.x & 31) == 0) ws[threadIdx.x >> 5] = val;
    __syncthreads();
    if (threadIdx.x == 0) {
        int s = 0;
        #pragma unroll
        for (int w = 0; w < 8; w++) s += ws[w];
        g_bsum[blockIdx.x] = s;
    }
}
__global__ __launch_bounds__(256) void scan_bsums(int nb, int n) {
    int tid = threadIdx.x;
    int val = (tid < nb) ? g_bsum[tid] : 0;
    int total;
    int excl = block_scan_excl(val, tid, &total);
    if (tid < nb) g_boff[tid] = excl;
    if (tid == 0) g_rowptr[n] = total;
}
__global__ __launch_bounds__(256) void scan_write(int n) {
    int i = blockIdx.x * 256 + threadIdx.x;
    int val = (i < n) ? (g_cnt[i] + 1) : 0;
    int excl = block_scan_excl(val, threadIdx.x, nullptr);
    if (i < n) {
        int p = g_boff[blockIdx.x] + excl;
        g_rowptr[i] = p;
        g_wptr[i] = p;
    }
}

__global__ void fill_kernel(const int* __restrict__ src, const int* __restrict__ dst,
                            int E, int n) {
    int b = (blockIdx.x * blockDim.x + threadIdx.x) * 4;
    #pragma unroll
    for (int j = 0; j < 4; j++) {
        int i = b + j;
        if (i < E) {
            int p = atomicAdd(&g_wptr[dst[i]], 1);
            g_col[p] = src[i];
        } else if (i < E + n) {
            int vtx = i - E;
            int p = atomicAdd(&g_wptr[vtx], 1);
            g_col[p] = vtx;
        }
    }
}

// ---------------- W prep: pack B fragments (hi/lo bf16 split) ----------------
__global__ void wprep_kernel(const float* __restrict__ W0, const float* __restrict__ W1,
                             const float* __restrict__ W2) {
    int idx = blockIdx.x * blockDim.x + threadIdx.x;
    const float* W;
    uint4* out;
    int N, local;
    if (idx < 4096)       { W = W0; out = g_bf0; N = 128; local = idx; }
    else if (idx < 8192)  { W = W1; out = g_bf1; N = 128; local = idx - 4096; }
    else if (idx < 10240) { W = W2; out = g_bf2; N = 64;  local = idx - 8192; }
    else return;
    int lane = local & 31;
    int ks = (local >> 5) & 7;
    int nb = local >> 8;
    int g = lane >> 2, t = lane & 3;
    int nn = nb * 8 + g;
    int k0 = ks * 16 + t * 2;
    float w00 = W[(k0 + 0) * N + nn], w01 = W[(k0 + 1) * N + nn];
    float w10 = W[(k0 + 8) * N + nn], w11 = W[(k0 + 9) * N + nn];
    __nv_bfloat16 h00 = __float2bfloat16(w00), h01 = __float2bfloat16(w01);
    __nv_bfloat16 h10 = __float2bfloat16(w10), h11 = __float2bfloat16(w11);
    uint4 o;
    o.x = pack_hi(w00, w01);
    o.y = pack_hi(w10, w11);
    o.z = pack_hi(w00 - __bfloat162float(h00), w01 - __bfloat162float(h01));
    o.w = pack_hi(w10 - __bfloat162float(h10), w11 - __bfloat162float(h11));
    out[local] = o;
}

// ---------------- bf16 mma GEMM + fused attention-score epilogue ----------------
__device__ __forceinline__ float silu(float v) { return v / (1.0f + __expf(-v)); }

template<int DOUT, bool ACT>
__global__ __launch_bounds__(256) void gemm_mma(
    const float* __restrict__ X, const uint4* __restrict__ Bf,
    const float* __restrict__ bin,
    const float* __restrict__ av_s, const float* __restrict__ av_d,
    float* __restrict__ O, int n)
{
    constexpr int NSTEP = DOUT / 8;
    constexpr int AST = 136;
    extern __shared__ __align__(16) char smem[];
    __nv_bfloat16* Ahi = (__nv_bfloat16*)smem;
    __nv_bfloat16* Alo = Ahi + 128 * AST;

    const int tid = threadIdx.x;
    const int wid = tid >> 5;
    const int lane = tid & 31;
    const int row0 = blockIdx.x * 128;

    for (int i = tid; i < 4096; i += 256) {
        int row = i >> 5, c4 = (i & 31) * 4;
        float4 v = make_float4(0.f, 0.f, 0.f, 0.f);
        if (row0 + row < n) v = *(const float4*)(X + (size_t)(row0 + row) * HD + c4);
        if (ACT) {
            v.x = silu(v.x + bin[c4 + 0]);
            v.y = silu(v.y + bin[c4 + 1]);
            v.z = silu(v.z + bin[c4 + 2]);
            v.w = silu(v.w + bin[c4 + 3]);
        }
        __nv_bfloat162 h01 = __floats2bfloat162_rn(v.x, v.y);
        __nv_bfloat162 h23 = __floats2bfloat162_rn(v.z, v.w);
        __nv_bfloat162 l01 = __floats2bfloat162_rn(v.x - __low2float(h01), v.y - __high2float(h01));
        __nv_bfloat162 l23 = __floats2bfloat162_rn(v.z - __low2float(h23), v.w - __high2float(h23));
        *(__nv_bfloat162*)(Ahi + row * AST + c4)     = h01;
        *(__nv_bfloat162*)(Ahi + row * AST + c4 + 2) = h23;
        *(__nv_bfloat162*)(Alo + row * AST + c4)     = l01;
        *(__nv_bfloat162*)(Alo + row * AST + c4 + 2) = l23;
    }
    __syncthreads();

    float acc[NSTEP][4];
    #pragma unroll
    for (int i = 0; i < NSTEP; i++) {
        acc[i][0] = acc[i][1] = acc[i][2] = acc[i][3] = 0.f;
    }

    const int arow = 16 * wid + (lane & 15);
    const int acol = (lane >> 4) * 8;
    const uint32_t ahi_base = smem_u32(Ahi + arow * AST + acol);
    const uint32_t alo_base = smem_u32(Alo + arow * AST + acol);

    #pragma unroll
    for (int ks = 0; ks < 8; ks++) {
        uint32_t ahi[4], alo[4];
        ldmatrix_x4(ahi, ahi_base + ks * 32);
        ldmatrix_x4(alo, alo_base + ks * 32);
        #pragma unroll
        for (int nb = 0; nb < NSTEP; nb++) {
            uint4 b = __ldg(&Bf[(nb * 8 + ks) * 32 + lane]);
            mma16816(acc[nb], ahi, b.x, b.y);
            mma16816(acc[nb], ahi, b.z, b.w);
            mma16816(acc[nb], alo, b.x, b.y);
        }
    }

    const int g = lane >> 2, t = lane & 3;
    const int r0 = row0 + 16 * wid + g;
    const int r1 = r0 + 8;
    float ss0 = 0.f, sd0 = 0.f, ss1 = 0.f, sd1 = 0.f;
    #pragma unroll
    for (int nb = 0; nb < NSTEP; nb++) {
        int c = nb * 8 + t * 2;
        float a0 = __ldg(&av_s[c]), a1 = __ldg(&av_s[c + 1]);
        float d0 = __ldg(&av_d[c]), d1 = __ldg(&av_d[c + 1]);
        ss0 += acc[nb][0] * a0 + acc[nb][1] * a1;
        sd0 += acc[nb][0] * d0 + acc[nb][1] * d1;
        ss1 += acc[nb][2] * a0 + acc[nb][3] * a1;
        sd1 += acc[nb][2] * d0 + acc[nb][3] * d1;
        if (r0 < n) *(float2*)(O + (size_t)r0 * DOUT + c) = make_float2(acc[nb][0], acc[nb][1]);
        if (r1 < n) *(float2*)(O + (size_t)r1 * DOUT + c) = make_float2(acc[nb][2], acc[nb][3]);
    }
    #pragma unroll
    for (int o = 1; o <= 2; o <<= 1) {
        ss0 += __shfl_xor_sync(0xffffffffu, ss0, o);
        sd0 += __shfl_xor_sync(0xffffffffu, sd0, o);
        ss1 += __shfl_xor_sync(0xffffffffu, ss1, o);
        sd1 += __shfl_xor_sync(0xffffffffu, sd1, o);
    }
    if (t == 0) {
        if (r0 < n) { g_ssrc[r0] = ss0; g_sdst[r0] = sd0; }
        if (r1 < n) { g_ssrc[r1] = ss1; g_sdst[r1] = sd1; }
    }
}

// ---------------- aggregation: single pass, 4-edge batches for MLP ----------------
template<int DOUT, bool FINAL>
__global__ __launch_bounds__(256) void agg_kernel(const float* __restrict__ Hin,
    float* __restrict__ out, const float* __restrict__ bias, int n)
{
    int gw = (blockIdx.x * blockDim.x + threadIdx.x) >> 5;
    int lane = threadIdx.x & 31;
    if (gw >= n) return;
    int beg = g_rowptr[gw], end = g_rowptr[gw + 1];
    float sd = g_sdst[gw];

    // stabilizer: this node's self-loop score (always a member of the max-set)
    float m = g_ssrc[gw] + sd;
    m = m > 0.f ? m : 0.2f * m;

    constexpr int V = DOUT / 32;
    float acc[V];
    #pragma unroll
    for (int t = 0; t < V; t++) acc[t] = 0.f;
    float denom = 0.f;

    int j = beg;
    for (; j + 3 < end; j += 4) {
        // batch 1: indices (independent)
        int s0 = g_col[j], s1 = g_col[j + 1], s2 = g_col[j + 2], s3 = g_col[j + 3];
        // batch 2: scores (independent gathers)
        float v0 = g_ssrc[s0], v1 = g_ssrc[s1], v2 = g_ssrc[s2], v3 = g_ssrc[s3];
        // batch 3: row gathers (4 independent wide loads in flight)
        if constexpr (V == 4) {
            float4 h0 = *(const float4*)(Hin + (size_t)s0 * DOUT + lane * 4);
            float4 h1 = *(const float4*)(Hin + (size_t)s1 * DOUT + lane * 4);
            float4 h2 = *(const float4*)(Hin + (size_t)s2 * DOUT + lane * 4);
            float4 h3 = *(const float4*)(Hin + (size_t)s3 * DOUT + lane * 4);
            v0 += sd; v1 += sd; v2 += sd; v3 += sd;
            v0 = v0 > 0.f ? v0 : 0.2f * v0;
            v1 = v1 > 0.f ? v1 : 0.2f * v1;
            v2 = v2 > 0.f ? v2 : 0.2f * v2;
            v3 = v3 > 0.f ? v3 : 0.2f * v3;
            float e0 = __expf(v0 - m), e1 = __expf(v1 - m);
            float e2 = __expf(v2 - m), e3 = __expf(v3 - m);
            denom += (e0 + e1) + (e2 + e3);
            acc[0] += e0 * h0.x + e1 * h1.x + e2 * h2.x + e3 * h3.x;
            acc[1] += e0 * h0.y + e1 * h1.y + e2 * h2.y + e3 * h3.y;
            acc[2] += e0 * h0.z + e1 * h1.z + e2 * h2.z + e3 * h3.z;
            acc[3] += e0 * h0.w + e1 * h1.w + e2 * h2.w + e3 * h3.w;
        } else {
            float2 h0 = *(const float2*)(Hin + (size_t)s0 * DOUT + lane * 2);
            float2 h1 = *(const float2*)(Hin + (size_t)s1 * DOUT + lane * 2);
            float2 h2 = *(const float2*)(Hin + (size_t)s2 * DOUT + lane * 2);
            float2 h3 = *(const float2*)(Hin + (size_t)s3 * DOUT + lane * 2);
            v0 += sd; v1 += sd; v2 += sd; v3 += sd;
            v0 = v0 > 0.f ? v0 : 0.2f * v0;
            v1 = v1 > 0.f ? v1 : 0.2f * v1;
            v2 = v2 > 0.f ? v2 : 0.2f * v2;
            v3 = v3 > 0.f ? v3 : 0.2f * v3;
            float e0 = __expf(v0 - m), e1 = __expf(v1 - m);
            float e2 = __expf(v2 - m), e3 = __expf(v3 - m);
            denom += (e0 + e1) + (e2 + e3);
            acc[0] += e0 * h0.x + e1 * h1.x + e2 * h2.x + e3 * h3.x;
            acc[1] += e0 * h0.y + e1 * h1.y + e2 * h2.y + e3 * h3.y;
        }
    }
    for (; j < end; j++) {
        int s0 = g_col[j];
        float v0 = g_ssrc[s0] + sd;
        v0 = v0 > 0.f ? v0 : 0.2f * v0;
        float e0 = __expf(v0 - m);
        denom += e0;
        if constexpr (V == 4) {
            float4 h0 = *(const float4*)(Hin + (size_t)s0 * DOUT + lane * 4);
            acc[0] += e0 * h0.x; acc[1] += e0 * h0.y;
            acc[2] += e0 * h0.z; acc[3] += e0 * h0.w;
        } else {
            float2 h0 = *(const float2*)(Hin + (size_t)s0 * DOUT + lane * 2);
            acc[0] += e0 * h0.x; acc[1] += e0 * h0.y;
        }
    }
    float inv = 1.0f / denom;

    if constexpr (!FINAL) {
        if constexpr (V == 4) {
            *(float4*)(out + (size_t)gw * DOUT + lane * 4) =
                make_float4(acc[0] * inv, acc[1] * inv, acc[2] * inv, acc[3] * inv);
        } else {
            *(float2*)(out + (size_t)gw * DOUT + lane * 2) =
                make_float2(acc[0] * inv, acc[1] * inv);
        }
    } else {
        float2 bb = *(const float2*)(bias + lane * 2);
        float x0 = acc[0] * inv + bb.x;
        float x1 = acc[1] * inv + bb.y;
        float mm = fmaxf(x0, x1);
        #pragma unroll
        for (int o = 16; o; o >>= 1) mm = fmaxf(mm, __shfl_xor_sync(0xffffffffu, mm, o));
        float s = __expf(x0 - mm) + __expf(x1 - mm);
        #pragma unroll
        for (int o = 16; o; o >>= 1) s += __shfl_xor_sync(0xffffffffu, s, o);
        float lse = mm + __logf(s);
        *(float2*)(out + (size_t)gw * 64 + lane * 2) = make_float2(x0 - lse, x1 - lse);
    }
}

// ---------------- launch ----------------
extern "C" void kernel_launch(void* const* d_in, const int* in_sizes, int n_in,
                              void* d_out, int out_size)
{
    const float* x   = (const float*)d_in[0];
    const int*   ei  = (const int*)d_in[1];
    const float* W0  = (const float*)d_in[2];
    const float* as0 = (const float*)d_in[3];
    const float* ad0 = (const float*)d_in[4];
    const float* b0  = (const float*)d_in[5];
    const float* W1  = (const float*)d_in[6];
    const float* as1 = (const float*)d_in[7];
    const float* ad1 = (const float*)d_in[8];
    const float* b1  = (const float*)d_in[9];
    const float* W2  = (const float*)d_in[10];
    const float* as2 = (const float*)d_in[11];
    const float* ad2 = (const float*)d_in[12];
    const float* b2  = (const float*)d_in[13];

    int n = in_sizes[0] / HD;
    int E = in_sizes[1] / 2;
    const int* src = ei;
    const int* dst = ei + E;

    float *h = nullptr, *agg = nullptr;
    uint4 *bf0, *bf1, *bf2;
    cudaGetSymbolAddress((void**)&h, g_h);
    cudaGetSymbolAddress((void**)&agg, g_agg);
    cudaGetSymbolAddress((void**)&bf0, g_bf0);
    cudaGetSymbolAddress((void**)&bf1, g_bf1);
    cudaGetSymbolAddress((void**)&bf2, g_bf2);

    const int smemA = 2 * 128 * 136 * 2;   // 69632 bytes
    cudaFuncSetAttribute(gemm_mma<128, false>, cudaFuncAttributeMaxDynamicSharedMemorySize, smemA);
    cudaFuncSetAttribute(gemm_mma<128, true>,  cudaFuncAttributeMaxDynamicSharedMemorySize, smemA);
    cudaFuncSetAttribute(gemm_mma<64, true>,   cudaFuncAttributeMaxDynamicSharedMemorySize, smemA);

    wprep_kernel<<<40, 256>>>(W0, W1, W2);

    int nb = (n + 255) / 256;
    zero_kernel<<<(n + 255) / 256, 256>>>(n);
    hist_kernel<<<(E / 4 + 255) / 256, 256>>>(dst, E);
    scan_reduce<<<nb, 256>>>(n);
    scan_bsums<<<1, 256>>>(nb, n);
    scan_write<<<nb, 256>>>(n);
    fill_kernel<<<((E + n + 3) / 4 + 255) / 256, 256>>>(src, dst, E, n);

    int gemmg = (n + 127) / 128;
    int warpg = (n * 32 + 255) / 256;

    gemm_mma<128, false><<<gemmg, 256, smemA>>>(x, bf0, nullptr, as0, ad0, h, n);
    agg_kernel<128, false><<<warpg, 256>>>(h, agg, nullptr, n);

    gemm_mma<128, true><<<gemmg, 256, smemA>>>(agg, bf1, b0, as1, ad1, h, n);
    agg_kernel<128, false><<<warpg, 256>>>(h, agg, nullptr, n);

    gemm_mma<64, true><<<gemmg, 256, smemA>>>(agg, bf2, b1, as2, ad2, h, n);
    agg_kernel<64, true><<<warpg, 256>>>(h, (float*)d_out, b2, n);
}